// round 1
// baseline (speedup 1.0000x reference)
#include <cuda_runtime.h>
#include <cuda_bf16.h>

#define T_   2048
#define B_   2
#define E_   1024
#define H_   16
#define HD_  64
#define ROWS (T_*B_)   // 4096

// Scratch (no cudaMalloc allowed)
__device__ float g_ln [ROWS * E_];        // 16 MB
__device__ float g_qkv[ROWS * 3 * E_];    // 48 MB
__device__ float g_ctx[ROWS * E_];        // 16 MB

// ---------------------------------------------------------------------------
// LayerNorm: one block per row (T*B rows), 256 threads, float4
// ---------------------------------------------------------------------------
__global__ void ln_kernel(const float* __restrict__ x,
                          const float* __restrict__ gamma,
                          const float* __restrict__ beta,
                          float* __restrict__ out) {
    int row = blockIdx.x;
    int tid = threadIdx.x;
    const float4* xr = (const float4*)(x + (size_t)row * E_);
    float4 v = xr[tid];
    float s  = v.x + v.y + v.z + v.w;
    float ss = v.x*v.x + v.y*v.y + v.z*v.z + v.w*v.w;
    #pragma unroll
    for (int o = 16; o; o >>= 1) {
        s  += __shfl_xor_sync(0xFFFFFFFFu, s,  o);
        ss += __shfl_xor_sync(0xFFFFFFFFu, ss, o);
    }
    __shared__ float rs[8], rss[8], stats[2];
    int w = tid >> 5, l = tid & 31;
    if (l == 0) { rs[w] = s; rss[w] = ss; }
    __syncthreads();
    if (w == 0) {
        s  = (l < 8) ? rs[l]  : 0.f;
        ss = (l < 8) ? rss[l] : 0.f;
        #pragma unroll
        for (int o = 4; o; o >>= 1) {
            s  += __shfl_xor_sync(0xFFFFFFFFu, s,  o);
            ss += __shfl_xor_sync(0xFFFFFFFFu, ss, o);
        }
        if (l == 0) {
            float mean = s * (1.f / E_);
            float var  = ss * (1.f / E_) - mean * mean;
            stats[0] = mean;
            stats[1] = rsqrtf(var + 1e-5f);
        }
    }
    __syncthreads();
    float mean = stats[0], rstd = stats[1];
    float4 gv = ((const float4*)gamma)[tid];
    float4 bv = ((const float4*)beta)[tid];
    float4 o4;
    o4.x = (v.x - mean) * rstd * gv.x + bv.x;
    o4.y = (v.y - mean) * rstd * gv.y + bv.y;
    o4.z = (v.z - mean) * rstd * gv.z + bv.z;
    o4.w = (v.w - mean) * rstd * gv.w + bv.w;
    ((float4*)(out + (size_t)row * E_))[tid] = o4;
}

// ---------------------------------------------------------------------------
// SGEMM NT: C[M,N] = A[M,K] * B[N,K]^T (+ resid). 128x128 block tile,
// 8x8 microtile, BK=8, 256 threads. M,N % 128 == 0, K % 8 == 0.
// ---------------------------------------------------------------------------
__global__ void __launch_bounds__(256, 2)
sgemm_nt(const float* __restrict__ A, const float* __restrict__ Bm,
         const float* __restrict__ resid, float* __restrict__ C,
         int M, int N, int K) {
    __shared__ float As[8][128];
    __shared__ float Bs[8][128];
    int tid = threadIdx.x;
    int m0 = blockIdx.y * 128, n0 = blockIdx.x * 128;
    int lrow = tid >> 1;
    int lk   = (tid & 1) * 4;
    int tx = tid & 15, ty = tid >> 4;

    const float* Ap = A  + (size_t)(m0 + lrow) * K + lk;
    const float* Bp = Bm + (size_t)(n0 + lrow) * K + lk;

    float acc[8][8];
    #pragma unroll
    for (int i = 0; i < 8; i++)
        #pragma unroll
        for (int j = 0; j < 8; j++) acc[i][j] = 0.f;

    for (int k0 = 0; k0 < K; k0 += 8) {
        float4 a4 = *(const float4*)(Ap + k0);
        float4 b4 = *(const float4*)(Bp + k0);
        __syncthreads();
        As[lk+0][lrow] = a4.x; As[lk+1][lrow] = a4.y;
        As[lk+2][lrow] = a4.z; As[lk+3][lrow] = a4.w;
        Bs[lk+0][lrow] = b4.x; Bs[lk+1][lrow] = b4.y;
        Bs[lk+2][lrow] = b4.z; Bs[lk+3][lrow] = b4.w;
        __syncthreads();
        #pragma unroll
        for (int kk = 0; kk < 8; kk++) {
            float a[8], b[8];
            #pragma unroll
            for (int i = 0; i < 8; i++) { a[i] = As[kk][ty*8+i]; b[i] = Bs[kk][tx*8+i]; }
            #pragma unroll
            for (int i = 0; i < 8; i++)
                #pragma unroll
                for (int j = 0; j < 8; j++)
                    acc[i][j] += a[i] * b[j];
        }
    }

    #pragma unroll
    for (int i = 0; i < 8; i++) {
        size_t rbase = (size_t)(m0 + ty*8 + i) * N + n0 + tx*8;
        #pragma unroll
        for (int j = 0; j < 8; j++) {
            float r = resid ? resid[rbase + j] : 0.f;
            C[rbase + j] = acc[i][j] + r;
        }
    }
}

// ---------------------------------------------------------------------------
// Flash-style attention. Block = (b,h, 64-query tile), 256 threads (8 warps),
// each warp owns 8 query rows; K/V streamed in 64-row tiles; online softmax.
// ---------------------------------------------------------------------------
__global__ void __launch_bounds__(256, 3)
attn_kernel(const float* __restrict__ qkv, float* __restrict__ ctx) {
    extern __shared__ float sm[];
    float* Qs = sm;                  // [64][64]
    float* Kt = sm + 4096;           // [64][65]  Kt[d*65+c] = K[c][d]
    float* Vs = sm + 4096 + 4160;    // [64][64]
    float* Ps = Vs + 4096;           // [64][64]

    int tid  = threadIdx.x;
    int lane = tid & 31, w = tid >> 5;
    int b = blockIdx.y & (B_ - 1);
    int h = blockIdx.y / B_;
    int q0 = blockIdx.x * 64;
    const float scale = 0.125f;      // HD^-0.5

    for (int idx = tid; idx < 64 * 64; idx += 256) {
        int r = idx >> 6, d = idx & 63;
        Qs[idx] = qkv[(size_t)((q0 + r) * B_ + b) * (3 * E_) + h * HD_ + d] * scale;
    }

    float m_i[8], l_i[8], o0[8], o1[8];
    #pragma unroll
    for (int i = 0; i < 8; i++) { m_i[i] = -1e30f; l_i[i] = 0.f; o0[i] = 0.f; o1[i] = 0.f; }

    for (int k0 = 0; k0 < T_; k0 += 64) {
        __syncthreads();
        for (int idx = tid; idx < 64 * 64; idx += 256) {
            int c = idx >> 6, d = idx & 63;
            size_t base = (size_t)((k0 + c) * B_ + b) * (3 * E_) + h * HD_ + d;
            Kt[d * 65 + c] = qkv[base + E_];
            Vs[c * 64 + d] = qkv[base + 2 * E_];
        }
        __syncthreads();

        // scores + online softmax (each lane: cols lane, lane+32)
        #pragma unroll
        for (int i = 0; i < 8; i++) {
            int r = w * 8 + i;
            const float* qrow = Qs + r * 64;
            float s0 = 0.f, s1 = 0.f;
            #pragma unroll 16
            for (int d = 0; d < 64; d++) {
                float qv = qrow[d];
                s0 += qv * Kt[d * 65 + lane];
                s1 += qv * Kt[d * 65 + lane + 32];
            }
            float mx = fmaxf(s0, s1);
            #pragma unroll
            for (int o = 16; o; o >>= 1) mx = fmaxf(mx, __shfl_xor_sync(0xFFFFFFFFu, mx, o));
            float mnew = fmaxf(m_i[i], mx);
            float p0 = __expf(s0 - mnew);
            float p1 = __expf(s1 - mnew);
            float corr = __expf(m_i[i] - mnew);
            m_i[i] = mnew;
            float rsum = p0 + p1;
            #pragma unroll
            for (int o = 16; o; o >>= 1) rsum += __shfl_xor_sync(0xFFFFFFFFu, rsum, o);
            l_i[i] = l_i[i] * corr + rsum;
            o0[i] *= corr; o1[i] *= corr;
            Ps[r * 64 + lane]      = p0;
            Ps[r * 64 + lane + 32] = p1;
        }
        __syncwarp();   // Ps rows are warp-private

        // O += P * V (lane owns dims lane, lane+32)
        #pragma unroll
        for (int i = 0; i < 8; i++) {
            int r = w * 8 + i;
            const float* prow = Ps + r * 64;
            float a0 = o0[i], a1 = o1[i];
            #pragma unroll 16
            for (int c = 0; c < 64; c++) {
                float p = prow[c];
                a0 += p * Vs[c * 64 + lane];
                a1 += p * Vs[c * 64 + lane + 32];
            }
            o0[i] = a0; o1[i] = a1;
        }
    }

    #pragma unroll
    for (int i = 0; i < 8; i++) {
        int r = w * 8 + i;
        float inv = 1.f / l_i[i];
        size_t base = (size_t)((q0 + r) * B_ + b) * E_ + h * HD_;
        ctx[base + lane]      = o0[i] * inv;
        ctx[base + lane + 32] = o1[i] * inv;
    }
}

// ---------------------------------------------------------------------------
extern "C" void kernel_launch(void* const* d_in, const int* in_sizes, int n_in,
                              void* d_out, int out_size) {
    (void)in_sizes; (void)n_in; (void)out_size;
    const float* query = (const float*)d_in[0];
    const float* gamma = (const float*)d_in[1];
    const float* beta  = (const float*)d_in[2];
    const float* Win   = (const float*)d_in[3];   // [3E, E]
    const float* Wout  = (const float*)d_in[4];   // [E, E]
    float* out = (float*)d_out;

    float *ln, *qkv, *ctx;
    cudaGetSymbolAddress((void**)&ln,  g_ln);
    cudaGetSymbolAddress((void**)&qkv, g_qkv);
    cudaGetSymbolAddress((void**)&ctx, g_ctx);

    // 1) LayerNorm
    ln_kernel<<<ROWS, 256>>>(query, gamma, beta, ln);

    // 2) QKV projection: [4096,1024] x [3072,1024]^T -> [4096,3072]
    dim3 g1(3 * E_ / 128, ROWS / 128);
    sgemm_nt<<<g1, 256>>>(ln, Win, nullptr, qkv, ROWS, 3 * E_, E_);

    // 3) Attention
    int smem = (4096 + 4160 + 4096 + 4096) * (int)sizeof(float);  // 65792 B
    cudaFuncSetAttribute(attn_kernel, cudaFuncAttributeMaxDynamicSharedMemorySize, smem);
    dim3 g2(T_ / 64, B_ * H_);
    attn_kernel<<<g2, 256, smem>>>(qkv, ctx);

    // 4) Output projection + residual: [4096,1024] x [1024,1024]^T + query
    dim3 g3(E_ / 128, ROWS / 128);
    sgemm_nt<<<g3, 256>>>(ctx, Wout, query, out, ROWS, E_, E_);
}

// round 2
// speedup vs baseline: 2.3386x; 2.3386x over previous
#include <cuda_runtime.h>
#include <cuda_bf16.h>
#include <cstdint>

#define T_   2048
#define B_   2
#define E_   1024
#define H_   16
#define HD_  64
#define ROWS (T_*B_)   // 4096

// Scratch (no cudaMalloc allowed)
__device__ float g_ln [ROWS * E_];        // 16 MB
__device__ float g_qkv[ROWS * 3 * E_];    // 48 MB
__device__ float g_ctx[ROWS * E_];        // 16 MB

__device__ __forceinline__ uint32_t f2tf32(float f) {
    uint32_t u;
    asm("cvt.rna.tf32.f32 %0, %1;" : "=r"(u) : "f"(f));
    return u;
}

// ---------------------------------------------------------------------------
// LayerNorm: one block per row (T*B rows), 256 threads, float4
// ---------------------------------------------------------------------------
__global__ void ln_kernel(const float* __restrict__ x,
                          const float* __restrict__ gamma,
                          const float* __restrict__ beta,
                          float* __restrict__ out) {
    int row = blockIdx.x;
    int tid = threadIdx.x;
    const float4* xr = (const float4*)(x + (size_t)row * E_);
    float4 v = xr[tid];
    float s  = v.x + v.y + v.z + v.w;
    float ss = v.x*v.x + v.y*v.y + v.z*v.z + v.w*v.w;
    #pragma unroll
    for (int o = 16; o; o >>= 1) {
        s  += __shfl_xor_sync(0xFFFFFFFFu, s,  o);
        ss += __shfl_xor_sync(0xFFFFFFFFu, ss, o);
    }
    __shared__ float rs[8], rss[8], stats[2];
    int w = tid >> 5, l = tid & 31;
    if (l == 0) { rs[w] = s; rss[w] = ss; }
    __syncthreads();
    if (w == 0) {
        s  = (l < 8) ? rs[l]  : 0.f;
        ss = (l < 8) ? rss[l] : 0.f;
        #pragma unroll
        for (int o = 4; o; o >>= 1) {
            s  += __shfl_xor_sync(0xFFFFFFFFu, s,  o);
            ss += __shfl_xor_sync(0xFFFFFFFFu, ss, o);
        }
        if (l == 0) {
            float mean = s * (1.f / E_);
            float var  = ss * (1.f / E_) - mean * mean;
            stats[0] = mean;
            stats[1] = rsqrtf(var + 1e-5f);
        }
    }
    __syncthreads();
    float mean = stats[0], rstd = stats[1];
    float4 gv = ((const float4*)gamma)[tid];
    float4 bv = ((const float4*)beta)[tid];
    float4 o4;
    o4.x = (v.x - mean) * rstd * gv.x + bv.x;
    o4.y = (v.y - mean) * rstd * gv.y + bv.y;
    o4.z = (v.z - mean) * rstd * gv.z + bv.z;
    o4.w = (v.w - mean) * rstd * gv.w + bv.w;
    ((float4*)(out + (size_t)row * E_))[tid] = o4;
}

// ---------------------------------------------------------------------------
// TF32 GEMM NT: C[M,N] = A[M,K]*B[N,K]^T (+resid).  128x128 tile, BK=16,
// 256 threads = 8 warps (2x4), warp tile 64x32, mma.sync m16n8k8 tf32.
// M,N % 128 == 0, K % 16 == 0.
// ---------------------------------------------------------------------------
#define BK_G 16
#define LDA_ (BK_G + 4)   // stride 20 floats: conflict-free fragment loads

__global__ void __launch_bounds__(256, 2)
gemm_tf32(const float* __restrict__ A, const float* __restrict__ Bm,
          const float* __restrict__ resid, float* __restrict__ C,
          int M, int N, int K) {
    __shared__ float As[2][128][LDA_];
    __shared__ float Bs[2][128][LDA_];

    int tid  = threadIdx.x;
    int lane = tid & 31, w = tid >> 5;
    int wm = w & 1, wn = w >> 1;            // warp grid 2(m) x 4(n)
    int m0b = blockIdx.y * 128, n0b = blockIdx.x * 128;

    // staging map: id -> (row = id>>2, kq = id&3), two ids per thread
    int r0 = tid >> 2, kq = tid & 3;        // ids tid and tid+256 -> rows r0, r0+64
    const float* Ap0 = A  + (size_t)(m0b + r0)      * K + 4 * kq;
    const float* Ap1 = A  + (size_t)(m0b + r0 + 64) * K + 4 * kq;
    const float* Bp0 = Bm + (size_t)(n0b + r0)      * K + 4 * kq;
    const float* Bp1 = Bm + (size_t)(n0b + r0 + 64) * K + 4 * kq;

    float acc[4][4][4];
    #pragma unroll
    for (int i = 0; i < 4; i++)
        #pragma unroll
        for (int j = 0; j < 4; j++)
            #pragma unroll
            for (int c = 0; c < 4; c++) acc[i][j][c] = 0.f;

    float4 ra0 = *(const float4*)Ap0;
    float4 ra1 = *(const float4*)Ap1;
    float4 rb0 = *(const float4*)Bp0;
    float4 rb1 = *(const float4*)Bp1;

    int buf = 0;
    for (int k0 = 0; k0 < K; k0 += BK_G) {
        // store (tf32-rounded) staged tile
        float* a0 = &As[buf][r0][4 * kq];
        float* a1 = &As[buf][r0 + 64][4 * kq];
        float* b0 = &Bs[buf][r0][4 * kq];
        float* b1 = &Bs[buf][r0 + 64][4 * kq];
        a0[0] = __uint_as_float(f2tf32(ra0.x)); a0[1] = __uint_as_float(f2tf32(ra0.y));
        a0[2] = __uint_as_float(f2tf32(ra0.z)); a0[3] = __uint_as_float(f2tf32(ra0.w));
        a1[0] = __uint_as_float(f2tf32(ra1.x)); a1[1] = __uint_as_float(f2tf32(ra1.y));
        a1[2] = __uint_as_float(f2tf32(ra1.z)); a1[3] = __uint_as_float(f2tf32(ra1.w));
        b0[0] = __uint_as_float(f2tf32(rb0.x)); b0[1] = __uint_as_float(f2tf32(rb0.y));
        b0[2] = __uint_as_float(f2tf32(rb0.z)); b0[3] = __uint_as_float(f2tf32(rb0.w));
        b1[0] = __uint_as_float(f2tf32(rb1.x)); b1[1] = __uint_as_float(f2tf32(rb1.y));
        b1[2] = __uint_as_float(f2tf32(rb1.z)); b1[3] = __uint_as_float(f2tf32(rb1.w));
        __syncthreads();

        if (k0 + BK_G < K) {
            ra0 = *(const float4*)(Ap0 + k0 + BK_G);
            ra1 = *(const float4*)(Ap1 + k0 + BK_G);
            rb0 = *(const float4*)(Bp0 + k0 + BK_G);
            rb1 = *(const float4*)(Bp1 + k0 + BK_G);
        }

        #pragma unroll
        for (int ks = 0; ks < 2; ks++) {
            uint32_t af[4][4], bf[4][2];
            int kk = ks * 8 + (lane & 3);
            int rr = lane >> 2;
            #pragma unroll
            for (int mt = 0; mt < 4; mt++) {
                const float* p = &As[buf][wm * 64 + mt * 16 + rr][kk];
                af[mt][0] = __float_as_uint(p[0]);
                af[mt][1] = __float_as_uint(p[8 * LDA_]);
                af[mt][2] = __float_as_uint(p[4]);
                af[mt][3] = __float_as_uint(p[8 * LDA_ + 4]);
            }
            #pragma unroll
            for (int nt = 0; nt < 4; nt++) {
                const float* p = &Bs[buf][wn * 32 + nt * 8 + rr][kk];
                bf[nt][0] = __float_as_uint(p[0]);
                bf[nt][1] = __float_as_uint(p[4]);
            }
            #pragma unroll
            for (int mt = 0; mt < 4; mt++)
                #pragma unroll
                for (int nt = 0; nt < 4; nt++) {
                    asm volatile(
                        "mma.sync.aligned.m16n8k8.row.col.f32.tf32.tf32.f32 "
                        "{%0,%1,%2,%3}, {%4,%5,%6,%7}, {%8,%9}, {%0,%1,%2,%3};"
                        : "+f"(acc[mt][nt][0]), "+f"(acc[mt][nt][1]),
                          "+f"(acc[mt][nt][2]), "+f"(acc[mt][nt][3])
                        : "r"(af[mt][0]), "r"(af[mt][1]), "r"(af[mt][2]), "r"(af[mt][3]),
                          "r"(bf[nt][0]), "r"(bf[nt][1]));
                }
        }
        buf ^= 1;
        __syncthreads();
    }

    // epilogue
    int mw = m0b + wm * 64, nw = n0b + wn * 32;
    #pragma unroll
    for (int mt = 0; mt < 4; mt++) {
        int row = mw + mt * 16 + (lane >> 2);
        #pragma unroll
        for (int nt = 0; nt < 4; nt++) {
            int col = nw + nt * 8 + (lane & 3) * 2;
            size_t i0 = (size_t)row * N + col;
            size_t i1 = (size_t)(row + 8) * N + col;
            float2 v0 = make_float2(acc[mt][nt][0], acc[mt][nt][1]);
            float2 v1 = make_float2(acc[mt][nt][2], acc[mt][nt][3]);
            if (resid) {
                float2 t0 = *(const float2*)(resid + i0);
                float2 t1 = *(const float2*)(resid + i1);
                v0.x += t0.x; v0.y += t0.y; v1.x += t1.x; v1.y += t1.y;
            }
            *(float2*)(C + i0) = v0;
            *(float2*)(C + i1) = v1;
        }
    }
}

// ---------------------------------------------------------------------------
// Flash-style attention (fp32, LDS-amortized). Block = (b,h, 64-query tile),
// 256 threads (8 warps), each warp owns 8 query rows.
// ---------------------------------------------------------------------------
__global__ void __launch_bounds__(256, 2)
attn_kernel(const float* __restrict__ qkv, float* __restrict__ ctx) {
    extern __shared__ float sm[];
    float* Qs = sm;                  // [64][64]
    float* Kt = sm + 4096;           // [64 d][65]  Kt[d*65+c] = K[c][d]
    float* Vs = sm + 4096 + 4160;    // [64][64]
    float* Ps = Vs + 4096;           // [64][64]

    int tid  = threadIdx.x;
    int lane = tid & 31, w = tid >> 5;
    int b = blockIdx.y & (B_ - 1);
    int h = blockIdx.y / B_;
    int q0 = blockIdx.x * 64;
    const float scale = 0.125f;      // HD^-0.5

    for (int idx = tid; idx < 64 * 64; idx += 256) {
        int r = idx >> 6, d = idx & 63;
        Qs[idx] = qkv[(size_t)((q0 + r) * B_ + b) * (3 * E_) + h * HD_ + d] * scale;
    }

    float m_i[8], l_i[8], o0[8], o1[8];
    #pragma unroll
    for (int i = 0; i < 8; i++) { m_i[i] = -1e30f; l_i[i] = 0.f; o0[i] = 0.f; o1[i] = 0.f; }

    for (int k0 = 0; k0 < T_; k0 += 64) {
        __syncthreads();
        for (int idx = tid; idx < 64 * 64; idx += 256) {
            int c = idx >> 6, d = idx & 63;
            size_t base = (size_t)((k0 + c) * B_ + b) * (3 * E_) + h * HD_ + d;
            Kt[d * 65 + c] = qkv[base + E_];
            Vs[c * 64 + d] = qkv[base + 2 * E_];
        }
        __syncthreads();

        // ---- scores: 8 rows x (cols lane, lane+32), LDS-amortized ----
        float s0[8], s1[8];
        #pragma unroll
        for (int i = 0; i < 8; i++) { s0[i] = 0.f; s1[i] = 0.f; }

        for (int d0 = 0; d0 < 64; d0 += 4) {
            float4 q[8];
            #pragma unroll
            for (int i = 0; i < 8; i++)
                q[i] = *(const float4*)(Qs + (w * 8 + i) * 64 + d0);
            #pragma unroll
            for (int j = 0; j < 4; j++) {
                float kk0 = Kt[(d0 + j) * 65 + lane];
                float kk1 = Kt[(d0 + j) * 65 + lane + 32];
                #pragma unroll
                for (int i = 0; i < 8; i++) {
                    float qv = (j == 0) ? q[i].x : (j == 1) ? q[i].y : (j == 2) ? q[i].z : q[i].w;
                    s0[i] += qv * kk0;
                    s1[i] += qv * kk1;
                }
            }
        }

        // ---- online softmax per row ----
        #pragma unroll
        for (int i = 0; i < 8; i++) {
            int r = w * 8 + i;
            float mx = fmaxf(s0[i], s1[i]);
            #pragma unroll
            for (int o = 16; o; o >>= 1) mx = fmaxf(mx, __shfl_xor_sync(0xFFFFFFFFu, mx, o));
            float mnew = fmaxf(m_i[i], mx);
            float p0 = __expf(s0[i] - mnew);
            float p1 = __expf(s1[i] - mnew);
            float corr = __expf(m_i[i] - mnew);
            m_i[i] = mnew;
            float rsum = p0 + p1;
            #pragma unroll
            for (int o = 16; o; o >>= 1) rsum += __shfl_xor_sync(0xFFFFFFFFu, rsum, o);
            l_i[i] = l_i[i] * corr + rsum;
            o0[i] *= corr; o1[i] *= corr;
            Ps[r * 64 + lane]      = p0;
            Ps[r * 64 + lane + 32] = p1;
        }
        __syncwarp();   // Ps rows are warp-private

        // ---- O += P * V, LDS-amortized (lane owns dims lane, lane+32) ----
        for (int c0 = 0; c0 < 64; c0 += 4) {
            float4 p[8];
            #pragma unroll
            for (int i = 0; i < 8; i++)
                p[i] = *(const float4*)(Ps + (w * 8 + i) * 64 + c0);
            #pragma unroll
            for (int j = 0; j < 4; j++) {
                float v0 = Vs[(c0 + j) * 64 + lane];
                float v1 = Vs[(c0 + j) * 64 + lane + 32];
                #pragma unroll
                for (int i = 0; i < 8; i++) {
                    float pv = (j == 0) ? p[i].x : (j == 1) ? p[i].y : (j == 2) ? p[i].z : p[i].w;
                    o0[i] += pv * v0;
                    o1[i] += pv * v1;
                }
            }
        }
        __syncwarp();
    }

    #pragma unroll
    for (int i = 0; i < 8; i++) {
        int r = w * 8 + i;
        float inv = 1.f / l_i[i];
        size_t base = (size_t)((q0 + r) * B_ + b) * E_ + h * HD_;
        ctx[base + lane]      = o0[i] * inv;
        ctx[base + lane + 32] = o1[i] * inv;
    }
}

// ---------------------------------------------------------------------------
extern "C" void kernel_launch(void* const* d_in, const int* in_sizes, int n_in,
                              void* d_out, int out_size) {
    (void)in_sizes; (void)n_in; (void)out_size;
    const float* query = (const float*)d_in[0];
    const float* gamma = (const float*)d_in[1];
    const float* beta  = (const float*)d_in[2];
    const float* Win   = (const float*)d_in[3];   // [3E, E]
    const float* Wout  = (const float*)d_in[4];   // [E, E]
    float* out = (float*)d_out;

    float *ln, *qkv, *ctx;
    cudaGetSymbolAddress((void**)&ln,  g_ln);
    cudaGetSymbolAddress((void**)&qkv, g_qkv);
    cudaGetSymbolAddress((void**)&ctx, g_ctx);

    // 1) LayerNorm
    ln_kernel<<<ROWS, 256>>>(query, gamma, beta, ln);

    // 2) QKV projection: [4096,1024] x [3072,1024]^T -> [4096,3072]
    dim3 g1(3 * E_ / 128, ROWS / 128);
    gemm_tf32<<<g1, 256>>>(ln, Win, nullptr, qkv, ROWS, 3 * E_, E_);

    // 3) Attention
    int smem = (4096 + 4160 + 4096 + 4096) * (int)sizeof(float);  // 65792 B
    cudaFuncSetAttribute(attn_kernel, cudaFuncAttributeMaxDynamicSharedMemorySize, smem);
    dim3 g2(T_ / 64, B_ * H_);
    attn_kernel<<<g2, 256, smem>>>(qkv, ctx);

    // 4) Output projection + residual: [4096,1024] x [1024,1024]^T + query
    dim3 g3(E_ / 128, ROWS / 128);
    gemm_tf32<<<g3, 256>>>(ctx, Wout, query, out, ROWS, E_, E_);
}

// round 3
// speedup vs baseline: 5.2206x; 2.2324x over previous
#include <cuda_runtime.h>
#include <cuda_bf16.h>
#include <cstdint>

#define T_   2048
#define B_   2
#define E_   1024
#define H_   16
#define HD_  64
#define ROWS (T_*B_)   // 4096

// Scratch (no cudaMalloc allowed)
__device__ float g_ln [ROWS * E_];        // 16 MB
__device__ float g_qkv[ROWS * 3 * E_];    // 48 MB
__device__ float g_ctx[ROWS * E_];        // 16 MB

__device__ __forceinline__ uint32_t f2tf32(float f) {
    uint32_t u;
    asm("cvt.rna.tf32.f32 %0, %1;" : "=r"(u) : "f"(f));
    return u;
}
__device__ __forceinline__ float tf32f(float f) { return __uint_as_float(f2tf32(f)); }

__device__ __forceinline__ void mma_tf32(float* c, uint32_t a0, uint32_t a1,
                                         uint32_t a2, uint32_t a3,
                                         uint32_t b0, uint32_t b1) {
    asm volatile(
        "mma.sync.aligned.m16n8k8.row.col.f32.tf32.tf32.f32 "
        "{%0,%1,%2,%3}, {%4,%5,%6,%7}, {%8,%9}, {%0,%1,%2,%3};"
        : "+f"(c[0]), "+f"(c[1]), "+f"(c[2]), "+f"(c[3])
        : "r"(a0), "r"(a1), "r"(a2), "r"(a3), "r"(b0), "r"(b1));
}

__device__ __forceinline__ void cp16(void* smem, const void* gmem) {
    uint32_t s = (uint32_t)__cvta_generic_to_shared(smem);
    asm volatile("cp.async.cg.shared.global [%0], [%1], 16;" :: "r"(s), "l"(gmem));
}

// ---------------------------------------------------------------------------
// LayerNorm
// ---------------------------------------------------------------------------
__global__ void ln_kernel(const float* __restrict__ x,
                          const float* __restrict__ gamma,
                          const float* __restrict__ beta,
                          float* __restrict__ out) {
    int row = blockIdx.x;
    int tid = threadIdx.x;
    const float4* xr = (const float4*)(x + (size_t)row * E_);
    float4 v = xr[tid];
    float s  = v.x + v.y + v.z + v.w;
    float ss = v.x*v.x + v.y*v.y + v.z*v.z + v.w*v.w;
    #pragma unroll
    for (int o = 16; o; o >>= 1) {
        s  += __shfl_xor_sync(0xFFFFFFFFu, s,  o);
        ss += __shfl_xor_sync(0xFFFFFFFFu, ss, o);
    }
    __shared__ float rs[8], rss[8], stats[2];
    int w = tid >> 5, l = tid & 31;
    if (l == 0) { rs[w] = s; rss[w] = ss; }
    __syncthreads();
    if (w == 0) {
        s  = (l < 8) ? rs[l]  : 0.f;
        ss = (l < 8) ? rss[l] : 0.f;
        #pragma unroll
        for (int o = 4; o; o >>= 1) {
            s  += __shfl_xor_sync(0xFFFFFFFFu, s,  o);
            ss += __shfl_xor_sync(0xFFFFFFFFu, ss, o);
        }
        if (l == 0) {
            float mean = s * (1.f / E_);
            float var  = ss * (1.f / E_) - mean * mean;
            stats[0] = mean;
            stats[1] = rsqrtf(var + 1e-5f);
        }
    }
    __syncthreads();
    float mean = stats[0], rstd = stats[1];
    float4 gv = ((const float4*)gamma)[tid];
    float4 bv = ((const float4*)beta)[tid];
    float4 o4;
    o4.x = (v.x - mean) * rstd * gv.x + bv.x;
    o4.y = (v.y - mean) * rstd * gv.y + bv.y;
    o4.z = (v.z - mean) * rstd * gv.z + bv.z;
    o4.w = (v.w - mean) * rstd * gv.w + bv.w;
    ((float4*)(out + (size_t)row * E_))[tid] = o4;
}

// ---------------------------------------------------------------------------
// TF32 GEMM NT: C = A[M,K]*B[N,K]^T (+resid). 128x128 tile, BK=16,
// 8 warps (2m x 4n), warp tile 64x32. Smem k-permuted for LDS.64 frag loads.
// ---------------------------------------------------------------------------
#define LDA_G 24                 // stride: 24 % 32 == 8 -> conflict-free LDS.64
#define GEMM_SMEM (2 * 2 * 128 * LDA_G * 4)   // 49152 B

__global__ void __launch_bounds__(256, 2)
gemm_tf32(const float* __restrict__ A, const float* __restrict__ Bm,
          const float* __restrict__ resid, float* __restrict__ C,
          int M, int N, int K) {
    extern __shared__ float smg[];
    float* As = smg;              // [2][128][24]
    float* Bs = smg + 2 * 128 * LDA_G;

    int tid  = threadIdx.x;
    int lane = tid & 31, w = tid >> 5;
    int q = lane & 3, rr = lane >> 2;
    int wm = w & 1, wn = w >> 1;
    int m0b = blockIdx.y * 128, n0b = blockIdx.x * 128;

    int r0 = tid >> 2, kq = tid & 3;
    int kb = (kq >> 1) * 8 + (kq & 1);    // permuted store base
    const float* Ap0 = A  + (size_t)(m0b + r0)      * K + 4 * kq;
    const float* Ap1 = A  + (size_t)(m0b + r0 + 64) * K + 4 * kq;
    const float* Bp0 = Bm + (size_t)(n0b + r0)      * K + 4 * kq;
    const float* Bp1 = Bm + (size_t)(n0b + r0 + 64) * K + 4 * kq;

    float acc[4][4][4];
    #pragma unroll
    for (int i = 0; i < 4; i++)
        #pragma unroll
        for (int j = 0; j < 4; j++)
            #pragma unroll
            for (int c = 0; c < 4; c++) acc[i][j][c] = 0.f;

    float4 ra0 = *(const float4*)Ap0;
    float4 ra1 = *(const float4*)Ap1;
    float4 rb0 = *(const float4*)Bp0;
    float4 rb1 = *(const float4*)Bp1;

    int buf = 0;
    for (int k0 = 0; k0 < K; k0 += 16) {
        float* a0 = As + buf * 3072 + r0 * LDA_G + kb;
        float* a1 = a0 + 64 * LDA_G;
        float* b0 = Bs + buf * 3072 + r0 * LDA_G + kb;
        float* b1 = b0 + 64 * LDA_G;
        a0[0]=tf32f(ra0.x); a0[2]=tf32f(ra0.y); a0[4]=tf32f(ra0.z); a0[6]=tf32f(ra0.w);
        a1[0]=tf32f(ra1.x); a1[2]=tf32f(ra1.y); a1[4]=tf32f(ra1.z); a1[6]=tf32f(ra1.w);
        b0[0]=tf32f(rb0.x); b0[2]=tf32f(rb0.y); b0[4]=tf32f(rb0.z); b0[6]=tf32f(rb0.w);
        b1[0]=tf32f(rb1.x); b1[2]=tf32f(rb1.y); b1[4]=tf32f(rb1.z); b1[6]=tf32f(rb1.w);
        __syncthreads();

        if (k0 + 16 < K) {
            ra0 = *(const float4*)(Ap0 + k0 + 16);
            ra1 = *(const float4*)(Ap1 + k0 + 16);
            rb0 = *(const float4*)(Bp0 + k0 + 16);
            rb1 = *(const float4*)(Bp1 + k0 + 16);
        }

        const float* Asb = As + buf * 3072;
        const float* Bsb = Bs + buf * 3072;
        #pragma unroll
        for (int ks = 0; ks < 2; ks++) {
            int c0 = ks * 8 + 2 * q;
            float2 alo[4], ahi[4], bb[4];
            #pragma unroll
            for (int mt = 0; mt < 4; mt++) {
                const float* p = Asb + (wm*64 + mt*16 + rr) * LDA_G + c0;
                alo[mt] = *(const float2*)p;
                ahi[mt] = *(const float2*)(p + 8 * LDA_G);
            }
            #pragma unroll
            for (int nt = 0; nt < 4; nt++)
                bb[nt] = *(const float2*)(Bsb + (wn*32 + nt*8 + rr) * LDA_G + c0);
            #pragma unroll
            for (int mt = 0; mt < 4; mt++)
                #pragma unroll
                for (int nt = 0; nt < 4; nt++)
                    mma_tf32(acc[mt][nt],
                             __float_as_uint(alo[mt].x), __float_as_uint(ahi[mt].x),
                             __float_as_uint(alo[mt].y), __float_as_uint(ahi[mt].y),
                             __float_as_uint(bb[nt].x),  __float_as_uint(bb[nt].y));
        }
        buf ^= 1;
        __syncthreads();
    }

    int mw = m0b + wm * 64, nw = n0b + wn * 32;
    #pragma unroll
    for (int mt = 0; mt < 4; mt++) {
        int row = mw + mt * 16 + rr;
        #pragma unroll
        for (int nt = 0; nt < 4; nt++) {
            int col = nw + nt * 8 + q * 2;
            size_t i0 = (size_t)row * N + col;
            size_t i1 = (size_t)(row + 8) * N + col;
            float2 v0 = make_float2(acc[mt][nt][0], acc[mt][nt][1]);
            float2 v1 = make_float2(acc[mt][nt][2], acc[mt][nt][3]);
            if (resid) {
                float2 t0 = *(const float2*)(resid + i0);
                float2 t1 = *(const float2*)(resid + i1);
                v0.x += t0.x; v0.y += t0.y; v1.x += t1.x; v1.y += t1.y;
            }
            *(float2*)(C + i0) = v0;
            *(float2*)(C + i1) = v1;
        }
    }
}

// ---------------------------------------------------------------------------
// Flash attention, tf32 mma. Block = 128 q rows x one (b,h). 8 warps,
// warp owns 16 rows (full 64 kv cols) -> softmax reductions are quad shuffles.
// K/V: cp.async double-buffered. K stride 68 (scalar b-frags conflict-free),
// V stride 72, Q stride 72 k-permuted (LDS.64 a-frags conflict-free).
// P never hits smem: accum->A-frag via 4-lane shuffle butterfly.
// ---------------------------------------------------------------------------
#define QS_LD 72
#define KS_LD 68
#define VS_LD 72
#define ATTN_SMEM ((128*QS_LD + 2*64*KS_LD + 2*64*VS_LD) * 4)   // 108544 B

__global__ void __launch_bounds__(256, 2)
attn_mma(const float* __restrict__ qkv, float* __restrict__ ctx) {
    extern __shared__ float sm[];
    float* Qs = sm;                          // [128][72]
    float* Ks = sm + 128 * QS_LD;            // [2][64][68]
    float* Vs = Ks + 2 * 64 * KS_LD;         // [2][64][72]

    int tid  = threadIdx.x;
    int lane = tid & 31, w = tid >> 5;
    int gr = lane >> 2, q = lane & 3;
    int b = blockIdx.y & 1, h = blockIdx.y >> 1;
    int q0 = blockIdx.x * 128;
    const float scale = 0.125f;

    // ---- issue cp.async for K/V tile ----
    auto issue_kv = [&](int k0, int buf) {
        #pragma unroll
        for (int i = 0; i < 4; i++) {
            int c = tid + 256 * i;
            int row = c >> 4, col4 = c & 15;
            const float* g = qkv + ((size_t)(k0 + row) * B_ + b) * (3 * E_) + h * HD_ + col4 * 4;
            cp16(Ks + buf * (64 * KS_LD) + row * KS_LD + col4 * 4, g + E_);
            cp16(Vs + buf * (64 * VS_LD) + row * VS_LD + col4 * 4, g + 2 * E_);
        }
        asm volatile("cp.async.commit_group;");
    };

    issue_kv(0, 0);

    // ---- stage Q (scaled, tf32-rounded, k-permuted) ----
    #pragma unroll
    for (int i = 0; i < 8; i++) {
        int c = tid + 256 * i;
        int row = c >> 4, col4 = c & 15;
        float4 v = *(const float4*)(qkv + ((size_t)(q0 + row) * B_ + b) * (3 * E_) + h * HD_ + col4 * 4);
        int kbq = (col4 >> 1) * 8 + (col4 & 1);
        float* qp = Qs + row * QS_LD + kbq;
        qp[0] = tf32f(v.x * scale); qp[2] = tf32f(v.y * scale);
        qp[4] = tf32f(v.z * scale); qp[6] = tf32f(v.w * scale);
    }

    float p[8][4], o[8][4];
    #pragma unroll
    for (int nt = 0; nt < 8; nt++)
        #pragma unroll
        for (int c = 0; c < 4; c++) o[nt][c] = 0.f;
    float m0 = -1e30f, m1 = -1e30f, l0 = 0.f, l1 = 0.f;

    for (int it = 0; it < T_ / 64; it++) {
        int buf = it & 1;
        if (it + 1 < T_ / 64) {
            issue_kv((it + 1) * 64, buf ^ 1);
            asm volatile("cp.async.wait_group 1;");
        } else {
            asm volatile("cp.async.wait_group 0;");
        }
        __syncthreads();

        const float* Kb = Ks + buf * (64 * KS_LD);
        const float* Vb = Vs + buf * (64 * VS_LD);

        // ---- S = Q K^T ----
        #pragma unroll
        for (int nt = 0; nt < 8; nt++)
            #pragma unroll
            for (int c = 0; c < 4; c++) p[nt][c] = 0.f;

        #pragma unroll
        for (int ks = 0; ks < 8; ks++) {
            const float* qp = Qs + (w * 16 + gr) * QS_LD + ks * 8 + 2 * q;
            float2 lo = *(const float2*)qp;
            float2 hi = *(const float2*)(qp + 8 * QS_LD);
            uint32_t a0 = __float_as_uint(lo.x), a1 = __float_as_uint(hi.x);
            uint32_t a2 = __float_as_uint(lo.y), a3 = __float_as_uint(hi.y);
            #pragma unroll
            for (int nt = 0; nt < 8; nt++) {
                const float* kp = Kb + (nt * 8 + gr) * KS_LD + ks * 8 + q;
                mma_tf32(p[nt], a0, a1, a2, a3,
                         __float_as_uint(kp[0]), __float_as_uint(kp[4]));
            }
        }

        // ---- online softmax (rows gr and gr+8; reduce over quad) ----
        float mx0 = -1e30f, mx1 = -1e30f;
        #pragma unroll
        for (int nt = 0; nt < 8; nt++) {
            mx0 = fmaxf(mx0, fmaxf(p[nt][0], p[nt][1]));
            mx1 = fmaxf(mx1, fmaxf(p[nt][2], p[nt][3]));
        }
        mx0 = fmaxf(mx0, __shfl_xor_sync(0xFFFFFFFFu, mx0, 1));
        mx0 = fmaxf(mx0, __shfl_xor_sync(0xFFFFFFFFu, mx0, 2));
        mx1 = fmaxf(mx1, __shfl_xor_sync(0xFFFFFFFFu, mx1, 1));
        mx1 = fmaxf(mx1, __shfl_xor_sync(0xFFFFFFFFu, mx1, 2));
        float mn0 = fmaxf(m0, mx0), mn1 = fmaxf(m1, mx1);
        float cr0 = __expf(m0 - mn0), cr1 = __expf(m1 - mn1);
        m0 = mn0; m1 = mn1;
        float s0 = 0.f, s1 = 0.f;
        #pragma unroll
        for (int nt = 0; nt < 8; nt++) {
            p[nt][0] = __expf(p[nt][0] - mn0);
            p[nt][1] = __expf(p[nt][1] - mn0);
            p[nt][2] = __expf(p[nt][2] - mn1);
            p[nt][3] = __expf(p[nt][3] - mn1);
            s0 += p[nt][0] + p[nt][1];
            s1 += p[nt][2] + p[nt][3];
        }
        s0 += __shfl_xor_sync(0xFFFFFFFFu, s0, 1);
        s0 += __shfl_xor_sync(0xFFFFFFFFu, s0, 2);
        s1 += __shfl_xor_sync(0xFFFFFFFFu, s1, 1);
        s1 += __shfl_xor_sync(0xFFFFFFFFu, s1, 2);
        l0 = l0 * cr0 + s0;
        l1 = l1 * cr1 + s1;
        #pragma unroll
        for (int nt = 0; nt < 8; nt++) {
            o[nt][0] *= cr0; o[nt][1] *= cr0;
            o[nt][2] *= cr1; o[nt][3] *= cr1;
            p[nt][0] = tf32f(p[nt][0]); p[nt][1] = tf32f(p[nt][1]);
            p[nt][2] = tf32f(p[nt][2]); p[nt][3] = tf32f(p[nt][3]);
        }

        // ---- O += P V : A-frag from accum via quad shuffle butterfly ----
        #pragma unroll
        for (int ks = 0; ks < 8; ks++) {
            int src0 = (lane & ~3) | (q >> 1);
            int src1 = src0 + 2;
            float x0 = __shfl_sync(0xFFFFFFFFu, p[ks][0], src0);
            float x1 = __shfl_sync(0xFFFFFFFFu, p[ks][1], src0);
            float y0 = __shfl_sync(0xFFFFFFFFu, p[ks][0], src1);
            float y1 = __shfl_sync(0xFFFFFFFFu, p[ks][1], src1);
            float z0 = __shfl_sync(0xFFFFFFFFu, p[ks][2], src0);
            float z1 = __shfl_sync(0xFFFFFFFFu, p[ks][3], src0);
            float u0 = __shfl_sync(0xFFFFFFFFu, p[ks][2], src1);
            float u1 = __shfl_sync(0xFFFFFFFFu, p[ks][3], src1);
            uint32_t a0 = __float_as_uint((q & 1) ? x1 : x0);
            uint32_t a2 = __float_as_uint((q & 1) ? y1 : y0);
            uint32_t a1 = __float_as_uint((q & 1) ? z1 : z0);
            uint32_t a3 = __float_as_uint((q & 1) ? u1 : u0);
            #pragma unroll
            for (int nt = 0; nt < 8; nt++) {
                const float* vp = Vb + (ks * 8 + q) * VS_LD + nt * 8 + gr;
                mma_tf32(o[nt], a0, a1, a2, a3,
                         __float_as_uint(vp[0]), __float_as_uint(vp[4 * VS_LD]));
            }
        }
        __syncthreads();
    }

    // ---- epilogue ----
    float i0 = 1.f / l0, i1 = 1.f / l1;
    int t0 = q0 + w * 16 + gr;
    #pragma unroll
    for (int nt = 0; nt < 8; nt++) {
        int d = h * HD_ + nt * 8 + 2 * q;
        *(float2*)(ctx + ((size_t)t0 * B_ + b) * E_ + d) =
            make_float2(o[nt][0] * i0, o[nt][1] * i0);
        *(float2*)(ctx + ((size_t)(t0 + 8) * B_ + b) * E_ + d) =
            make_float2(o[nt][2] * i1, o[nt][3] * i1);
    }
}

// ---------------------------------------------------------------------------
extern "C" void kernel_launch(void* const* d_in, const int* in_sizes, int n_in,
                              void* d_out, int out_size) {
    (void)in_sizes; (void)n_in; (void)out_size;
    const float* query = (const float*)d_in[0];
    const float* gamma = (const float*)d_in[1];
    const float* beta  = (const float*)d_in[2];
    const float* Win   = (const float*)d_in[3];   // [3E, E]
    const float* Wout  = (const float*)d_in[4];   // [E, E]
    float* out = (float*)d_out;

    float *ln, *qkv, *ctx;
    cudaGetSymbolAddress((void**)&ln,  g_ln);
    cudaGetSymbolAddress((void**)&qkv, g_qkv);
    cudaGetSymbolAddress((void**)&ctx, g_ctx);

    cudaFuncSetAttribute(gemm_tf32, cudaFuncAttributeMaxDynamicSharedMemorySize, GEMM_SMEM);
    cudaFuncSetAttribute(attn_mma,  cudaFuncAttributeMaxDynamicSharedMemorySize, ATTN_SMEM);

    // 1) LayerNorm
    ln_kernel<<<ROWS, 256>>>(query, gamma, beta, ln);

    // 2) QKV projection
    dim3 g1(3 * E_ / 128, ROWS / 128);
    gemm_tf32<<<g1, 256, GEMM_SMEM>>>(ln, Win, nullptr, qkv, ROWS, 3 * E_, E_);

    // 3) Attention
    dim3 g2(T_ / 128, B_ * H_);
    attn_mma<<<g2, 256, ATTN_SMEM>>>(qkv, ctx);

    // 4) Output projection + residual
    dim3 g3(E_ / 128, ROWS / 128);
    gemm_tf32<<<g3, 256, GEMM_SMEM>>>(ctx, Wout, query, out, ROWS, E_, E_);
}

// round 4
// speedup vs baseline: 7.8752x; 1.5085x over previous
#include <cuda_runtime.h>
#include <cuda_bf16.h>
#include <cstdint>

#define T_   2048
#define B_   2
#define E_   1024
#define H_   16
#define HD_  64
#define ROWS (T_*B_)   // 4096

// Scratch (no cudaMalloc allowed)
__device__ __nv_bfloat16 g_lnb[ROWS * E_];        // 8 MB  (LN output, bf16)
__device__ float         g_qkv[ROWS * 3 * E_];    // 48 MB (QKV, fp32)
__device__ __nv_bfloat16 g_ctxb[ROWS * E_];       // 8 MB  (attn out, bf16)
__device__ __nv_bfloat16 g_wb[4 * E_ * E_];       // 8 MB  (Win | Wout, bf16)

__device__ __forceinline__ uint32_t f2tf32(float f) {
    uint32_t u;
    asm("cvt.rna.tf32.f32 %0, %1;" : "=r"(u) : "f"(f));
    return u;
}
__device__ __forceinline__ float tf32f(float f) { return __uint_as_float(f2tf32(f)); }

__device__ __forceinline__ void mma_tf32(float* c, uint32_t a0, uint32_t a1,
                                         uint32_t a2, uint32_t a3,
                                         uint32_t b0, uint32_t b1) {
    asm volatile(
        "mma.sync.aligned.m16n8k8.row.col.f32.tf32.tf32.f32 "
        "{%0,%1,%2,%3}, {%4,%5,%6,%7}, {%8,%9}, {%0,%1,%2,%3};"
        : "+f"(c[0]), "+f"(c[1]), "+f"(c[2]), "+f"(c[3])
        : "r"(a0), "r"(a1), "r"(a2), "r"(a3), "r"(b0), "r"(b1));
}

__device__ __forceinline__ void mma_bf16(float* c, uint32_t a0, uint32_t a1,
                                         uint32_t a2, uint32_t a3,
                                         uint32_t b0, uint32_t b1) {
    asm volatile(
        "mma.sync.aligned.m16n8k16.row.col.f32.bf16.bf16.f32 "
        "{%0,%1,%2,%3}, {%4,%5,%6,%7}, {%8,%9}, {%0,%1,%2,%3};"
        : "+f"(c[0]), "+f"(c[1]), "+f"(c[2]), "+f"(c[3])
        : "r"(a0), "r"(a1), "r"(a2), "r"(a3), "r"(b0), "r"(b1));
}

__device__ __forceinline__ void ldsm4(uint32_t& r0, uint32_t& r1, uint32_t& r2,
                                      uint32_t& r3, const void* p) {
    uint32_t a = (uint32_t)__cvta_generic_to_shared(p);
    asm volatile("ldmatrix.sync.aligned.m8n8.x4.shared.b16 {%0,%1,%2,%3}, [%4];"
                 : "=r"(r0), "=r"(r1), "=r"(r2), "=r"(r3) : "r"(a));
}

__device__ __forceinline__ void cp16(void* smem, const void* gmem) {
    uint32_t s = (uint32_t)__cvta_generic_to_shared(smem);
    asm volatile("cp.async.cg.shared.global [%0], [%1], 16;" :: "r"(s), "l"(gmem));
}

// ---------------------------------------------------------------------------
// LayerNorm -> bf16 output
// ---------------------------------------------------------------------------
__global__ void ln_kernel(const float* __restrict__ x,
                          const float* __restrict__ gamma,
                          const float* __restrict__ beta,
                          __nv_bfloat16* __restrict__ out) {
    int row = blockIdx.x;
    int tid = threadIdx.x;
    const float4* xr = (const float4*)(x + (size_t)row * E_);
    float4 v = xr[tid];
    float s  = v.x + v.y + v.z + v.w;
    float ss = v.x*v.x + v.y*v.y + v.z*v.z + v.w*v.w;
    #pragma unroll
    for (int o = 16; o; o >>= 1) {
        s  += __shfl_xor_sync(0xFFFFFFFFu, s,  o);
        ss += __shfl_xor_sync(0xFFFFFFFFu, ss, o);
    }
    __shared__ float rs[8], rss[8], stats[2];
    int w = tid >> 5, l = tid & 31;
    if (l == 0) { rs[w] = s; rss[w] = ss; }
    __syncthreads();
    if (w == 0) {
        s  = (l < 8) ? rs[l]  : 0.f;
        ss = (l < 8) ? rss[l] : 0.f;
        #pragma unroll
        for (int o = 4; o; o >>= 1) {
            s  += __shfl_xor_sync(0xFFFFFFFFu, s,  o);
            ss += __shfl_xor_sync(0xFFFFFFFFu, ss, o);
        }
        if (l == 0) {
            float mean = s * (1.f / E_);
            float var  = ss * (1.f / E_) - mean * mean;
            stats[0] = mean;
            stats[1] = rsqrtf(var + 1e-5f);
        }
    }
    __syncthreads();
    float mean = stats[0], rstd = stats[1];
    float4 gv = ((const float4*)gamma)[tid];
    float4 bv = ((const float4*)beta)[tid];
    float ox = (v.x - mean) * rstd * gv.x + bv.x;
    float oy = (v.y - mean) * rstd * gv.y + bv.y;
    float oz = (v.z - mean) * rstd * gv.z + bv.z;
    float ow = (v.w - mean) * rstd * gv.w + bv.w;
    __nv_bfloat162* op = (__nv_bfloat162*)(out + (size_t)row * E_);
    op[2*tid]   = __floats2bfloat162_rn(ox, oy);
    op[2*tid+1] = __floats2bfloat162_rn(oz, ow);
}

// ---------------------------------------------------------------------------
// fp32 -> bf16 weight convert
// ---------------------------------------------------------------------------
__global__ void conv_w(const float4* __restrict__ in,
                       __nv_bfloat162* __restrict__ out, int n4) {
    int i = blockIdx.x * blockDim.x + threadIdx.x;
    if (i < n4) {
        float4 v = in[i];
        out[2*i]   = __floats2bfloat162_rn(v.x, v.y);
        out[2*i+1] = __floats2bfloat162_rn(v.z, v.w);
    }
}

// ---------------------------------------------------------------------------
// BF16 GEMM NT: C[M,N](fp32) = A[M,K]*B[N,K]^T (+resid fp32).
// 128x128 tile, BK=32, 8 warps (2m x 4n), warp 64x32, ldmatrix + HMMA.16816,
// cp.async double-buffered. smem row stride 40 bf16 (80B): conflict-free LDSM.
// ---------------------------------------------------------------------------
#define LDB_ 40

__global__ void __launch_bounds__(256, 2)
gemm_bf16(const __nv_bfloat16* __restrict__ A, const __nv_bfloat16* __restrict__ Bm,
          const float* __restrict__ resid, float* __restrict__ C,
          int M, int N, int K) {
    __shared__ __nv_bfloat16 As[2][128][LDB_];
    __shared__ __nv_bfloat16 Bs[2][128][LDB_];

    int tid  = threadIdx.x;
    int lane = tid & 31, w = tid >> 5;
    int q = lane & 3, rr = lane >> 2;
    int wm = w & 1, wn = w >> 1;
    int m0b = blockIdx.y * 128, n0b = blockIdx.x * 128;

    // staging: ids tid, tid+256 -> row=id>>2, chunk=id&3 (8 bf16 = 16B)
    int r0 = tid >> 2, ch = tid & 3;
    const __nv_bfloat16* Ap0 = A  + (size_t)(m0b + r0)      * K + ch * 8;
    const __nv_bfloat16* Ap1 = A  + (size_t)(m0b + r0 + 64) * K + ch * 8;
    const __nv_bfloat16* Bp0 = Bm + (size_t)(n0b + r0)      * K + ch * 8;
    const __nv_bfloat16* Bp1 = Bm + (size_t)(n0b + r0 + 64) * K + ch * 8;

    auto stage = [&](int k0, int buf) {
        cp16(&As[buf][r0][ch * 8],      Ap0 + k0);
        cp16(&As[buf][r0 + 64][ch * 8], Ap1 + k0);
        cp16(&Bs[buf][r0][ch * 8],      Bp0 + k0);
        cp16(&Bs[buf][r0 + 64][ch * 8], Bp1 + k0);
        asm volatile("cp.async.commit_group;");
    };

    float acc[4][4][4];
    #pragma unroll
    for (int i = 0; i < 4; i++)
        #pragma unroll
        for (int j = 0; j < 4; j++)
            #pragma unroll
            for (int c = 0; c < 4; c++) acc[i][j][c] = 0.f;

    stage(0, 0);

    int buf = 0;
    for (int k0 = 0; k0 < K; k0 += 32) {
        if (k0 + 32 < K) {
            stage(k0 + 32, buf ^ 1);
            asm volatile("cp.async.wait_group 1;");
        } else {
            asm volatile("cp.async.wait_group 0;");
        }
        __syncthreads();

        #pragma unroll
        for (int ks = 0; ks < 2; ks++) {
            uint32_t a[4][4], bfr[2][4];
            // A frags: lanes 0-15 rows, lane>>4 selects k-half
            #pragma unroll
            for (int mt = 0; mt < 4; mt++) {
                const __nv_bfloat16* p =
                    &As[buf][wm*64 + mt*16 + (lane & 15)][ks*16 + (lane >> 4) * 8];
                ldsm4(a[mt][0], a[mt][1], a[mt][2], a[mt][3], p);
            }
            // B frag pairs: each x4 covers two nt tiles (16 n rows)
            #pragma unroll
            for (int np = 0; np < 2; np++) {
                int row = wn*32 + np*16 + ((lane >> 4) << 3) + (lane & 7);
                int col = ks*16 + ((lane >> 3) & 1) * 8;
                const __nv_bfloat16* p = &Bs[buf][row][col];
                ldsm4(bfr[np][0], bfr[np][1], bfr[np][2], bfr[np][3], p);
            }
            #pragma unroll
            for (int mt = 0; mt < 4; mt++)
                #pragma unroll
                for (int nt = 0; nt < 4; nt++) {
                    uint32_t b0 = bfr[nt >> 1][(nt & 1) * 2];
                    uint32_t b1 = bfr[nt >> 1][(nt & 1) * 2 + 1];
                    mma_bf16(acc[mt][nt], a[mt][0], a[mt][1], a[mt][2], a[mt][3], b0, b1);
                }
        }
        buf ^= 1;
        __syncthreads();
    }

    int mw = m0b + wm * 64, nw = n0b + wn * 32;
    #pragma unroll
    for (int mt = 0; mt < 4; mt++) {
        int row = mw + mt * 16 + rr;
        #pragma unroll
        for (int nt = 0; nt < 4; nt++) {
            int col = nw + nt * 8 + q * 2;
            size_t i0 = (size_t)row * N + col;
            size_t i1 = (size_t)(row + 8) * N + col;
            float2 v0 = make_float2(acc[mt][nt][0], acc[mt][nt][1]);
            float2 v1 = make_float2(acc[mt][nt][2], acc[mt][nt][3]);
            if (resid) {
                float2 t0 = *(const float2*)(resid + i0);
                float2 t1 = *(const float2*)(resid + i1);
                v0.x += t0.x; v0.y += t0.y; v1.x += t1.x; v1.y += t1.y;
            }
            *(float2*)(C + i0) = v0;
            *(float2*)(C + i1) = v1;
        }
    }
}

// ---------------------------------------------------------------------------
// Flash attention, tf32 mma (unchanged except bf16 ctx output).
// ---------------------------------------------------------------------------
#define QS_LD 72
#define KS_LD 68
#define VS_LD 72
#define ATTN_SMEM ((128*QS_LD + 2*64*KS_LD + 2*64*VS_LD) * 4)   // 108544 B

__global__ void __launch_bounds__(256, 2)
attn_mma(const float* __restrict__ qkv, __nv_bfloat16* __restrict__ ctx) {
    extern __shared__ float sm[];
    float* Qs = sm;
    float* Ks = sm + 128 * QS_LD;
    float* Vs = Ks + 2 * 64 * KS_LD;

    int tid  = threadIdx.x;
    int lane = tid & 31, w = tid >> 5;
    int gr = lane >> 2, q = lane & 3;
    int b = blockIdx.y & 1, h = blockIdx.y >> 1;
    int q0 = blockIdx.x * 128;
    const float scale = 0.125f;

    auto issue_kv = [&](int k0, int buf) {
        #pragma unroll
        for (int i = 0; i < 4; i++) {
            int c = tid + 256 * i;
            int row = c >> 4, col4 = c & 15;
            const float* g = qkv + ((size_t)(k0 + row) * B_ + b) * (3 * E_) + h * HD_ + col4 * 4;
            cp16(Ks + buf * (64 * KS_LD) + row * KS_LD + col4 * 4, g + E_);
            cp16(Vs + buf * (64 * VS_LD) + row * VS_LD + col4 * 4, g + 2 * E_);
        }
        asm volatile("cp.async.commit_group;");
    };

    issue_kv(0, 0);

    #pragma unroll
    for (int i = 0; i < 8; i++) {
        int c = tid + 256 * i;
        int row = c >> 4, col4 = c & 15;
        float4 v = *(const float4*)(qkv + ((size_t)(q0 + row) * B_ + b) * (3 * E_) + h * HD_ + col4 * 4);
        int kbq = (col4 >> 1) * 8 + (col4 & 1);
        float* qp = Qs + row * QS_LD + kbq;
        qp[0] = tf32f(v.x * scale); qp[2] = tf32f(v.y * scale);
        qp[4] = tf32f(v.z * scale); qp[6] = tf32f(v.w * scale);
    }

    float p[8][4], o[8][4];
    #pragma unroll
    for (int nt = 0; nt < 8; nt++)
        #pragma unroll
        for (int c = 0; c < 4; c++) o[nt][c] = 0.f;
    float m0 = -1e30f, m1 = -1e30f, l0 = 0.f, l1 = 0.f;

    for (int it = 0; it < T_ / 64; it++) {
        int buf = it & 1;
        if (it + 1 < T_ / 64) {
            issue_kv((it + 1) * 64, buf ^ 1);
            asm volatile("cp.async.wait_group 1;");
        } else {
            asm volatile("cp.async.wait_group 0;");
        }
        __syncthreads();

        const float* Kb = Ks + buf * (64 * KS_LD);
        const float* Vb = Vs + buf * (64 * VS_LD);

        #pragma unroll
        for (int nt = 0; nt < 8; nt++)
            #pragma unroll
            for (int c = 0; c < 4; c++) p[nt][c] = 0.f;

        #pragma unroll
        for (int ks = 0; ks < 8; ks++) {
            const float* qp = Qs + (w * 16 + gr) * QS_LD + ks * 8 + 2 * q;
            float2 lo = *(const float2*)qp;
            float2 hi = *(const float2*)(qp + 8 * QS_LD);
            uint32_t a0 = __float_as_uint(lo.x), a1 = __float_as_uint(hi.x);
            uint32_t a2 = __float_as_uint(lo.y), a3 = __float_as_uint(hi.y);
            #pragma unroll
            for (int nt = 0; nt < 8; nt++) {
                const float* kp = Kb + (nt * 8 + gr) * KS_LD + ks * 8 + q;
                mma_tf32(p[nt], a0, a1, a2, a3,
                         __float_as_uint(kp[0]), __float_as_uint(kp[4]));
            }
        }

        float mx0 = -1e30f, mx1 = -1e30f;
        #pragma unroll
        for (int nt = 0; nt < 8; nt++) {
            mx0 = fmaxf(mx0, fmaxf(p[nt][0], p[nt][1]));
            mx1 = fmaxf(mx1, fmaxf(p[nt][2], p[nt][3]));
        }
        mx0 = fmaxf(mx0, __shfl_xor_sync(0xFFFFFFFFu, mx0, 1));
        mx0 = fmaxf(mx0, __shfl_xor_sync(0xFFFFFFFFu, mx0, 2));
        mx1 = fmaxf(mx1, __shfl_xor_sync(0xFFFFFFFFu, mx1, 1));
        mx1 = fmaxf(mx1, __shfl_xor_sync(0xFFFFFFFFu, mx1, 2));
        float mn0 = fmaxf(m0, mx0), mn1 = fmaxf(m1, mx1);
        float cr0 = __expf(m0 - mn0), cr1 = __expf(m1 - mn1);
        m0 = mn0; m1 = mn1;
        float s0 = 0.f, s1 = 0.f;
        #pragma unroll
        for (int nt = 0; nt < 8; nt++) {
            p[nt][0] = __expf(p[nt][0] - mn0);
            p[nt][1] = __expf(p[nt][1] - mn0);
            p[nt][2] = __expf(p[nt][2] - mn1);
            p[nt][3] = __expf(p[nt][3] - mn1);
            s0 += p[nt][0] + p[nt][1];
            s1 += p[nt][2] + p[nt][3];
        }
        s0 += __shfl_xor_sync(0xFFFFFFFFu, s0, 1);
        s0 += __shfl_xor_sync(0xFFFFFFFFu, s0, 2);
        s1 += __shfl_xor_sync(0xFFFFFFFFu, s1, 1);
        s1 += __shfl_xor_sync(0xFFFFFFFFu, s1, 2);
        l0 = l0 * cr0 + s0;
        l1 = l1 * cr1 + s1;
        #pragma unroll
        for (int nt = 0; nt < 8; nt++) {
            o[nt][0] *= cr0; o[nt][1] *= cr0;
            o[nt][2] *= cr1; o[nt][3] *= cr1;
            p[nt][0] = tf32f(p[nt][0]); p[nt][1] = tf32f(p[nt][1]);
            p[nt][2] = tf32f(p[nt][2]); p[nt][3] = tf32f(p[nt][3]);
        }

        #pragma unroll
        for (int ks = 0; ks < 8; ks++) {
            int src0 = (lane & ~3) | (q >> 1);
            int src1 = src0 + 2;
            float x0 = __shfl_sync(0xFFFFFFFFu, p[ks][0], src0);
            float x1 = __shfl_sync(0xFFFFFFFFu, p[ks][1], src0);
            float y0 = __shfl_sync(0xFFFFFFFFu, p[ks][0], src1);
            float y1 = __shfl_sync(0xFFFFFFFFu, p[ks][1], src1);
            float z0 = __shfl_sync(0xFFFFFFFFu, p[ks][2], src0);
            float z1 = __shfl_sync(0xFFFFFFFFu, p[ks][3], src0);
            float u0 = __shfl_sync(0xFFFFFFFFu, p[ks][2], src1);
            float u1 = __shfl_sync(0xFFFFFFFFu, p[ks][3], src1);
            uint32_t a0 = __float_as_uint((q & 1) ? x1 : x0);
            uint32_t a2 = __float_as_uint((q & 1) ? y1 : y0);
            uint32_t a1 = __float_as_uint((q & 1) ? z1 : z0);
            uint32_t a3 = __float_as_uint((q & 1) ? u1 : u0);
            #pragma unroll
            for (int nt = 0; nt < 8; nt++) {
                const float* vp = Vb + (ks * 8 + q) * VS_LD + nt * 8 + gr;
                mma_tf32(o[nt], a0, a1, a2, a3,
                         __float_as_uint(vp[0]), __float_as_uint(vp[4 * VS_LD]));
            }
        }
        __syncthreads();
    }

    float i0 = 1.f / l0, i1 = 1.f / l1;
    int t0 = q0 + w * 16 + gr;
    #pragma unroll
    for (int nt = 0; nt < 8; nt++) {
        int d = h * HD_ + nt * 8 + 2 * q;
        *(__nv_bfloat162*)(ctx + ((size_t)t0 * B_ + b) * E_ + d) =
            __floats2bfloat162_rn(o[nt][0] * i0, o[nt][1] * i0);
        *(__nv_bfloat162*)(ctx + ((size_t)(t0 + 8) * B_ + b) * E_ + d) =
            __floats2bfloat162_rn(o[nt][2] * i1, o[nt][3] * i1);
    }
}

// ---------------------------------------------------------------------------
extern "C" void kernel_launch(void* const* d_in, const int* in_sizes, int n_in,
                              void* d_out, int out_size) {
    (void)in_sizes; (void)n_in; (void)out_size;
    const float* query = (const float*)d_in[0];
    const float* gamma = (const float*)d_in[1];
    const float* beta  = (const float*)d_in[2];
    const float* Win   = (const float*)d_in[3];   // [3E, E]
    const float* Wout  = (const float*)d_in[4];   // [E, E]
    float* out = (float*)d_out;

    __nv_bfloat16 *lnb, *ctxb, *wb;
    float *qkv;
    cudaGetSymbolAddress((void**)&lnb,  g_lnb);
    cudaGetSymbolAddress((void**)&qkv,  g_qkv);
    cudaGetSymbolAddress((void**)&ctxb, g_ctxb);
    cudaGetSymbolAddress((void**)&wb,   g_wb);
    __nv_bfloat16* winb  = wb;
    __nv_bfloat16* woutb = wb + 3 * E_ * E_;

    cudaFuncSetAttribute(attn_mma, cudaFuncAttributeMaxDynamicSharedMemorySize, ATTN_SMEM);

    // 0) weights -> bf16
    conv_w<<<(3 * E_ * E_ / 4 + 255) / 256, 256>>>((const float4*)Win,
                                                   (__nv_bfloat162*)winb, 3 * E_ * E_ / 4);
    conv_w<<<(E_ * E_ / 4 + 255) / 256, 256>>>((const float4*)Wout,
                                               (__nv_bfloat162*)woutb, E_ * E_ / 4);

    // 1) LayerNorm -> bf16
    ln_kernel<<<ROWS, 256>>>(query, gamma, beta, lnb);

    // 2) QKV projection (bf16 in, fp32 out)
    dim3 g1(3 * E_ / 128, ROWS / 128);
    gemm_bf16<<<g1, 256>>>(lnb, winb, nullptr, qkv, ROWS, 3 * E_, E_);

    // 3) Attention (tf32), ctx out bf16
    dim3 g2(T_ / 128, B_ * H_);
    attn_mma<<<g2, 256, ATTN_SMEM>>>(qkv, ctxb);

    // 4) Output projection + residual (bf16 in, fp32 out)
    dim3 g3(E_ / 128, ROWS / 128);
    gemm_bf16<<<g3, 256>>>(ctxb, woutb, query, out, ROWS, E_, E_);
}

// round 5
// speedup vs baseline: 11.2123x; 1.4238x over previous
#include <cuda_runtime.h>
#include <cuda_bf16.h>
#include <cstdint>

#define T_   2048
#define B_   2
#define E_   1024
#define H_   16
#define HD_  64
#define ROWS (T_*B_)   // 4096

// Scratch (no cudaMalloc allowed)
__device__ __nv_bfloat16 g_lnb [ROWS * E_];        // 8 MB  (LN output, bf16)
__device__ __nv_bfloat16 g_qkvb[ROWS * 3 * E_];    // 24 MB (QKV, bf16)
__device__ __nv_bfloat16 g_ctxb[ROWS * E_];        // 8 MB  (attn out, bf16)
__device__ __nv_bfloat16 g_wb  [4 * E_ * E_];      // 8 MB  (Win | Wout, bf16)

__device__ __forceinline__ void mma_bf16(float* c, uint32_t a0, uint32_t a1,
                                         uint32_t a2, uint32_t a3,
                                         uint32_t b0, uint32_t b1) {
    asm volatile(
        "mma.sync.aligned.m16n8k16.row.col.f32.bf16.bf16.f32 "
        "{%0,%1,%2,%3}, {%4,%5,%6,%7}, {%8,%9}, {%0,%1,%2,%3};"
        : "+f"(c[0]), "+f"(c[1]), "+f"(c[2]), "+f"(c[3])
        : "r"(a0), "r"(a1), "r"(a2), "r"(a3), "r"(b0), "r"(b1));
}

__device__ __forceinline__ void ldsm4(uint32_t& r0, uint32_t& r1, uint32_t& r2,
                                      uint32_t& r3, const void* p) {
    uint32_t a = (uint32_t)__cvta_generic_to_shared(p);
    asm volatile("ldmatrix.sync.aligned.m8n8.x4.shared.b16 {%0,%1,%2,%3}, [%4];"
                 : "=r"(r0), "=r"(r1), "=r"(r2), "=r"(r3) : "r"(a));
}

__device__ __forceinline__ void ldsm4t(uint32_t& r0, uint32_t& r1, uint32_t& r2,
                                       uint32_t& r3, const void* p) {
    uint32_t a = (uint32_t)__cvta_generic_to_shared(p);
    asm volatile("ldmatrix.sync.aligned.m8n8.x4.trans.shared.b16 {%0,%1,%2,%3}, [%4];"
                 : "=r"(r0), "=r"(r1), "=r"(r2), "=r"(r3) : "r"(a));
}

__device__ __forceinline__ void cp16(void* smem, const void* gmem) {
    uint32_t s = (uint32_t)__cvta_generic_to_shared(smem);
    asm volatile("cp.async.cg.shared.global [%0], [%1], 16;" :: "r"(s), "l"(gmem));
}

__device__ __forceinline__ uint32_t packbf(float lo, float hi) {
    __nv_bfloat162 v = __floats2bfloat162_rn(lo, hi);
    return *(uint32_t*)&v;
}

// ---------------------------------------------------------------------------
// LayerNorm -> bf16 output
// ---------------------------------------------------------------------------
__global__ void ln_kernel(const float* __restrict__ x,
                          const float* __restrict__ gamma,
                          const float* __restrict__ beta,
                          __nv_bfloat16* __restrict__ out) {
    int row = blockIdx.x;
    int tid = threadIdx.x;
    const float4* xr = (const float4*)(x + (size_t)row * E_);
    float4 v = xr[tid];
    float s  = v.x + v.y + v.z + v.w;
    float ss = v.x*v.x + v.y*v.y + v.z*v.z + v.w*v.w;
    #pragma unroll
    for (int o = 16; o; o >>= 1) {
        s  += __shfl_xor_sync(0xFFFFFFFFu, s,  o);
        ss += __shfl_xor_sync(0xFFFFFFFFu, ss, o);
    }
    __shared__ float rs[8], rss[8], stats[2];
    int w = tid >> 5, l = tid & 31;
    if (l == 0) { rs[w] = s; rss[w] = ss; }
    __syncthreads();
    if (w == 0) {
        s  = (l < 8) ? rs[l]  : 0.f;
        ss = (l < 8) ? rss[l] : 0.f;
        #pragma unroll
        for (int o = 4; o; o >>= 1) {
            s  += __shfl_xor_sync(0xFFFFFFFFu, s,  o);
            ss += __shfl_xor_sync(0xFFFFFFFFu, ss, o);
        }
        if (l == 0) {
            float mean = s * (1.f / E_);
            float var  = ss * (1.f / E_) - mean * mean;
            stats[0] = mean;
            stats[1] = rsqrtf(var + 1e-5f);
        }
    }
    __syncthreads();
    float mean = stats[0], rstd = stats[1];
    float4 gv = ((const float4*)gamma)[tid];
    float4 bv = ((const float4*)beta)[tid];
    float ox = (v.x - mean) * rstd * gv.x + bv.x;
    float oy = (v.y - mean) * rstd * gv.y + bv.y;
    float oz = (v.z - mean) * rstd * gv.z + bv.z;
    float ow = (v.w - mean) * rstd * gv.w + bv.w;
    __nv_bfloat162* op = (__nv_bfloat162*)(out + (size_t)row * E_);
    op[2*tid]   = __floats2bfloat162_rn(ox, oy);
    op[2*tid+1] = __floats2bfloat162_rn(oz, ow);
}

// ---------------------------------------------------------------------------
// fp32 -> bf16 weight convert
// ---------------------------------------------------------------------------
__global__ void conv_w(const float4* __restrict__ in,
                       __nv_bfloat162* __restrict__ out, int n4) {
    int i = blockIdx.x * blockDim.x + threadIdx.x;
    if (i < n4) {
        float4 v = in[i];
        out[2*i]   = __floats2bfloat162_rn(v.x, v.y);
        out[2*i+1] = __floats2bfloat162_rn(v.z, v.w);
    }
}

// ---------------------------------------------------------------------------
// BF16 GEMM NT: A[M,K]*B[N,K]^T. Output: Cb (bf16) if non-null, else
// C (fp32, +resid). 128x128 tile, BK=32, 8 warps, ldmatrix + HMMA.16816.
// ---------------------------------------------------------------------------
#define LDB_ 40

__global__ void __launch_bounds__(256, 2)
gemm_bf16(const __nv_bfloat16* __restrict__ A, const __nv_bfloat16* __restrict__ Bm,
          const float* __restrict__ resid, float* __restrict__ C,
          __nv_bfloat16* __restrict__ Cb,
          int M, int N, int K) {
    __shared__ __nv_bfloat16 As[2][128][LDB_];
    __shared__ __nv_bfloat16 Bs[2][128][LDB_];

    int tid  = threadIdx.x;
    int lane = tid & 31, w = tid >> 5;
    int q = lane & 3, rr = lane >> 2;
    int wm = w & 1, wn = w >> 1;
    int m0b = blockIdx.y * 128, n0b = blockIdx.x * 128;

    int r0 = tid >> 2, ch = tid & 3;
    const __nv_bfloat16* Ap0 = A  + (size_t)(m0b + r0)      * K + ch * 8;
    const __nv_bfloat16* Ap1 = A  + (size_t)(m0b + r0 + 64) * K + ch * 8;
    const __nv_bfloat16* Bp0 = Bm + (size_t)(n0b + r0)      * K + ch * 8;
    const __nv_bfloat16* Bp1 = Bm + (size_t)(n0b + r0 + 64) * K + ch * 8;

    auto stage = [&](int k0, int buf) {
        cp16(&As[buf][r0][ch * 8],      Ap0 + k0);
        cp16(&As[buf][r0 + 64][ch * 8], Ap1 + k0);
        cp16(&Bs[buf][r0][ch * 8],      Bp0 + k0);
        cp16(&Bs[buf][r0 + 64][ch * 8], Bp1 + k0);
        asm volatile("cp.async.commit_group;");
    };

    float acc[4][4][4];
    #pragma unroll
    for (int i = 0; i < 4; i++)
        #pragma unroll
        for (int j = 0; j < 4; j++)
            #pragma unroll
            for (int c = 0; c < 4; c++) acc[i][j][c] = 0.f;

    stage(0, 0);

    int buf = 0;
    for (int k0 = 0; k0 < K; k0 += 32) {
        if (k0 + 32 < K) {
            stage(k0 + 32, buf ^ 1);
            asm volatile("cp.async.wait_group 1;");
        } else {
            asm volatile("cp.async.wait_group 0;");
        }
        __syncthreads();

        #pragma unroll
        for (int ks = 0; ks < 2; ks++) {
            uint32_t a[4][4], bfr[2][4];
            #pragma unroll
            for (int mt = 0; mt < 4; mt++) {
                const __nv_bfloat16* p =
                    &As[buf][wm*64 + mt*16 + (lane & 15)][ks*16 + (lane >> 4) * 8];
                ldsm4(a[mt][0], a[mt][1], a[mt][2], a[mt][3], p);
            }
            #pragma unroll
            for (int np = 0; np < 2; np++) {
                int row = wn*32 + np*16 + ((lane >> 4) << 3) + (lane & 7);
                int col = ks*16 + ((lane >> 3) & 1) * 8;
                const __nv_bfloat16* p = &Bs[buf][row][col];
                ldsm4(bfr[np][0], bfr[np][1], bfr[np][2], bfr[np][3], p);
            }
            #pragma unroll
            for (int mt = 0; mt < 4; mt++)
                #pragma unroll
                for (int nt = 0; nt < 4; nt++) {
                    uint32_t b0 = bfr[nt >> 1][(nt & 1) * 2];
                    uint32_t b1 = bfr[nt >> 1][(nt & 1) * 2 + 1];
                    mma_bf16(acc[mt][nt], a[mt][0], a[mt][1], a[mt][2], a[mt][3], b0, b1);
                }
        }
        buf ^= 1;
        __syncthreads();
    }

    int mw = m0b + wm * 64, nw = n0b + wn * 32;
    #pragma unroll
    for (int mt = 0; mt < 4; mt++) {
        int row = mw + mt * 16 + rr;
        #pragma unroll
        for (int nt = 0; nt < 4; nt++) {
            int col = nw + nt * 8 + q * 2;
            size_t i0 = (size_t)row * N + col;
            size_t i1 = (size_t)(row + 8) * N + col;
            if (Cb) {
                *(__nv_bfloat162*)(Cb + i0) =
                    __floats2bfloat162_rn(acc[mt][nt][0], acc[mt][nt][1]);
                *(__nv_bfloat162*)(Cb + i1) =
                    __floats2bfloat162_rn(acc[mt][nt][2], acc[mt][nt][3]);
            } else {
                float2 v0 = make_float2(acc[mt][nt][0], acc[mt][nt][1]);
                float2 v1 = make_float2(acc[mt][nt][2], acc[mt][nt][3]);
                if (resid) {
                    float2 t0 = *(const float2*)(resid + i0);
                    float2 t1 = *(const float2*)(resid + i1);
                    v0.x += t0.x; v0.y += t0.y; v1.x += t1.x; v1.y += t1.y;
                }
                *(float2*)(C + i0) = v0;
                *(float2*)(C + i1) = v1;
            }
        }
    }
}

// ---------------------------------------------------------------------------
// Flash attention, bf16 HMMA. Block = 128 q rows x one (b,h). 8 warps,
// warp owns 16 rows x full 64 kv cols. K row-major = B-operand of QK^T;
// V via ldmatrix.trans. P accum maps directly onto A-frags (no shuffles).
// smem stride 72 bf16 (144B): conflict-free for normal + trans ldmatrix.
// ---------------------------------------------------------------------------
#define AT_LD 72
#define ATTN_SMEM ((128 * AT_LD + 2 * 64 * AT_LD + 2 * 64 * AT_LD) * 2)  // 55296 B

__global__ void __launch_bounds__(256, 2)
attn_bf16(const __nv_bfloat16* __restrict__ qkv, __nv_bfloat16* __restrict__ ctx) {
    extern __shared__ char smraw[];
    __nv_bfloat16* Qs = (__nv_bfloat16*)smraw;          // [128][72]
    __nv_bfloat16* Ks = Qs + 128 * AT_LD;               // [2][64][72]
    __nv_bfloat16* Vs = Ks + 2 * 64 * AT_LD;            // [2][64][72]

    int tid  = threadIdx.x;
    int lane = tid & 31, w = tid >> 5;
    int gr = lane >> 2, q = lane & 3;
    int b = blockIdx.y & 1, h = blockIdx.y >> 1;
    int q0 = blockIdx.x * 128;

    // ---- stage Q (cp.async): 128 rows x 8 chunks of 8 bf16 ----
    #pragma unroll
    for (int i = 0; i < 4; i++) {
        int c = tid + 256 * i;
        int row = c >> 3, ch = c & 7;
        const __nv_bfloat16* g =
            qkv + ((size_t)(q0 + row) * B_ + b) * (3 * E_) + h * HD_ + ch * 8;
        cp16(Qs + row * AT_LD + ch * 8, g);
    }

    // ---- K/V tile loader: 64 rows x 8 chunks each ----
    auto issue_kv = [&](int k0, int buf) {
        __nv_bfloat16* Kb = Ks + buf * (64 * AT_LD);
        __nv_bfloat16* Vb = Vs + buf * (64 * AT_LD);
        #pragma unroll
        for (int i = 0; i < 4; i++) {
            int c = tid + 256 * i;          // 0..1023
            int kv = c >> 9;                // 0: K, 1: V
            int idx = c & 511;
            int row = idx >> 3, ch = idx & 7;
            const __nv_bfloat16* g =
                qkv + ((size_t)(k0 + row) * B_ + b) * (3 * E_) + h * HD_ + ch * 8
                    + (kv ? 2 * E_ : E_);
            cp16((kv ? Vb : Kb) + row * AT_LD + ch * 8, g);
        }
        asm volatile("cp.async.commit_group;");
    };

    issue_kv(0, 0);   // group 0 = Q + KV0

    float p[8][4], o[8][4];
    #pragma unroll
    for (int nt = 0; nt < 8; nt++)
        #pragma unroll
        for (int c = 0; c < 4; c++) o[nt][c] = 0.f;
    float m0 = -1e30f, m1 = -1e30f, l0 = 0.f, l1 = 0.f;

    for (int it = 0; it < T_ / 64; it++) {
        int buf = it & 1;
        if (it + 1 < T_ / 64) {
            issue_kv((it + 1) * 64, buf ^ 1);
            asm volatile("cp.async.wait_group 1;");
        } else {
            asm volatile("cp.async.wait_group 0;");
        }
        __syncthreads();

        const __nv_bfloat16* Kb = Ks + buf * (64 * AT_LD);
        const __nv_bfloat16* Vb = Vs + buf * (64 * AT_LD);

        // ---- S = Q K^T ----
        #pragma unroll
        for (int nt = 0; nt < 8; nt++)
            #pragma unroll
            for (int c = 0; c < 4; c++) p[nt][c] = 0.f;

        #pragma unroll
        for (int ks = 0; ks < 4; ks++) {
            uint32_t a0, a1, a2, a3;
            ldsm4(a0, a1, a2, a3,
                  Qs + (w * 16 + (lane & 15)) * AT_LD + ks * 16 + (lane >> 4) * 8);
            #pragma unroll
            for (int np = 0; np < 4; np++) {
                uint32_t b0, b1, b2, b3;
                int row = np * 16 + ((lane >> 4) << 3) + (lane & 7);
                int col = ks * 16 + ((lane >> 3) & 1) * 8;
                ldsm4(b0, b1, b2, b3, Kb + row * AT_LD + col);
                mma_bf16(p[2 * np],     a0, a1, a2, a3, b0, b1);
                mma_bf16(p[2 * np + 1], a0, a1, a2, a3, b2, b3);
            }
        }

        // ---- scale + online softmax (rows gr, gr+8; quad reduce) ----
        float mx0 = -1e30f, mx1 = -1e30f;
        #pragma unroll
        for (int nt = 0; nt < 8; nt++) {
            p[nt][0] *= 0.125f; p[nt][1] *= 0.125f;
            p[nt][2] *= 0.125f; p[nt][3] *= 0.125f;
            mx0 = fmaxf(mx0, fmaxf(p[nt][0], p[nt][1]));
            mx1 = fmaxf(mx1, fmaxf(p[nt][2], p[nt][3]));
        }
        mx0 = fmaxf(mx0, __shfl_xor_sync(0xFFFFFFFFu, mx0, 1));
        mx0 = fmaxf(mx0, __shfl_xor_sync(0xFFFFFFFFu, mx0, 2));
        mx1 = fmaxf(mx1, __shfl_xor_sync(0xFFFFFFFFu, mx1, 1));
        mx1 = fmaxf(mx1, __shfl_xor_sync(0xFFFFFFFFu, mx1, 2));
        float mn0 = fmaxf(m0, mx0), mn1 = fmaxf(m1, mx1);
        float cr0 = __expf(m0 - mn0), cr1 = __expf(m1 - mn1);
        m0 = mn0; m1 = mn1;
        float s0 = 0.f, s1 = 0.f;
        #pragma unroll
        for (int nt = 0; nt < 8; nt++) {
            p[nt][0] = __expf(p[nt][0] - mn0);
            p[nt][1] = __expf(p[nt][1] - mn0);
            p[nt][2] = __expf(p[nt][2] - mn1);
            p[nt][3] = __expf(p[nt][3] - mn1);
            s0 += p[nt][0] + p[nt][1];
            s1 += p[nt][2] + p[nt][3];
        }
        s0 += __shfl_xor_sync(0xFFFFFFFFu, s0, 1);
        s0 += __shfl_xor_sync(0xFFFFFFFFu, s0, 2);
        s1 += __shfl_xor_sync(0xFFFFFFFFu, s1, 1);
        s1 += __shfl_xor_sync(0xFFFFFFFFu, s1, 2);
        l0 = l0 * cr0 + s0;
        l1 = l1 * cr1 + s1;
        #pragma unroll
        for (int nt = 0; nt < 8; nt++) {
            o[nt][0] *= cr0; o[nt][1] *= cr0;
            o[nt][2] *= cr1; o[nt][3] *= cr1;
        }

        // ---- O += P V : A-frags straight from P accumulators ----
        #pragma unroll
        for (int ks = 0; ks < 4; ks++) {
            uint32_t a0 = packbf(p[2*ks][0],   p[2*ks][1]);
            uint32_t a1 = packbf(p[2*ks][2],   p[2*ks][3]);
            uint32_t a2 = packbf(p[2*ks+1][0], p[2*ks+1][1]);
            uint32_t a3 = packbf(p[2*ks+1][2], p[2*ks+1][3]);
            #pragma unroll
            for (int np = 0; np < 4; np++) {
                uint32_t b0, b1, b2, b3;
                // trans load: rows = kv s, cols = d
                int row = ks * 16 + (lane & 15);
                int col = np * 16 + (lane >> 4) * 8;
                ldsm4t(b0, b1, b2, b3, Vb + row * AT_LD + col);
                mma_bf16(o[2 * np],     a0, a1, a2, a3, b0, b1);
                mma_bf16(o[2 * np + 1], a0, a1, a2, a3, b2, b3);
            }
        }
        __syncthreads();
    }

    // ---- epilogue ----
    float i0 = 1.f / l0, i1 = 1.f / l1;
    int t0 = q0 + w * 16 + gr;
    #pragma unroll
    for (int nt = 0; nt < 8; nt++) {
        int d = h * HD_ + nt * 8 + 2 * q;
        *(__nv_bfloat162*)(ctx + ((size_t)t0 * B_ + b) * E_ + d) =
            __floats2bfloat162_rn(o[nt][0] * i0, o[nt][1] * i0);
        *(__nv_bfloat162*)(ctx + ((size_t)(t0 + 8) * B_ + b) * E_ + d) =
            __floats2bfloat162_rn(o[nt][2] * i1, o[nt][3] * i1);
    }
}

// ---------------------------------------------------------------------------
extern "C" void kernel_launch(void* const* d_in, const int* in_sizes, int n_in,
                              void* d_out, int out_size) {
    (void)in_sizes; (void)n_in; (void)out_size;
    const float* query = (const float*)d_in[0];
    const float* gamma = (const float*)d_in[1];
    const float* beta  = (const float*)d_in[2];
    const float* Win   = (const float*)d_in[3];   // [3E, E]
    const float* Wout  = (const float*)d_in[4];   // [E, E]
    float* out = (float*)d_out;

    __nv_bfloat16 *lnb, *qkvb, *ctxb, *wb;
    cudaGetSymbolAddress((void**)&lnb,  g_lnb);
    cudaGetSymbolAddress((void**)&qkvb, g_qkvb);
    cudaGetSymbolAddress((void**)&ctxb, g_ctxb);
    cudaGetSymbolAddress((void**)&wb,   g_wb);
    __nv_bfloat16* winb  = wb;
    __nv_bfloat16* woutb = wb + 3 * E_ * E_;

    cudaFuncSetAttribute(attn_bf16, cudaFuncAttributeMaxDynamicSharedMemorySize, ATTN_SMEM);

    // 0) weights -> bf16
    conv_w<<<(3 * E_ * E_ / 4 + 255) / 256, 256>>>((const float4*)Win,
                                                   (__nv_bfloat162*)winb, 3 * E_ * E_ / 4);
    conv_w<<<(E_ * E_ / 4 + 255) / 256, 256>>>((const float4*)Wout,
                                               (__nv_bfloat162*)woutb, E_ * E_ / 4);

    // 1) LayerNorm -> bf16
    ln_kernel<<<ROWS, 256>>>(query, gamma, beta, lnb);

    // 2) QKV projection (bf16 in, bf16 out)
    dim3 g1(3 * E_ / 128, ROWS / 128);
    gemm_bf16<<<g1, 256>>>(lnb, winb, nullptr, nullptr, qkvb, ROWS, 3 * E_, E_);

    // 3) Attention (bf16), ctx out bf16
    dim3 g2(T_ / 128, B_ * H_);
    attn_bf16<<<g2, 256, ATTN_SMEM>>>(qkvb, ctxb);

    // 4) Output projection + residual (bf16 in, fp32 out)
    dim3 g3(E_ / 128, ROWS / 128);
    gemm_bf16<<<g3, 256>>>(ctxb, woutb, query, out, nullptr, ROWS, E_, E_);
}

// round 8
// speedup vs baseline: 11.3424x; 1.0116x over previous
#include <cuda_runtime.h>
#include <cuda_bf16.h>
#include <cstdint>

#define T_   2048
#define B_   2
#define E_   1024
#define H_   16
#define HD_  64
#define ROWS (T_*B_)   // 4096

// Scratch (no cudaMalloc allowed)
__device__ __nv_bfloat16 g_lnb [ROWS * E_];        // 8 MB
__device__ __nv_bfloat16 g_qkvb[ROWS * 3 * E_];    // 24 MB
__device__ __nv_bfloat16 g_ctxb[ROWS * E_];        // 8 MB
__device__ __nv_bfloat16 g_wb  [4 * E_ * E_];      // 8 MB

__device__ __forceinline__ void mma_bf16(float* c, uint32_t a0, uint32_t a1,
                                         uint32_t a2, uint32_t a3,
                                         uint32_t b0, uint32_t b1) {
    asm volatile(
        "mma.sync.aligned.m16n8k16.row.col.f32.bf16.bf16.f32 "
        "{%0,%1,%2,%3}, {%4,%5,%6,%7}, {%8,%9}, {%0,%1,%2,%3};"
        : "+f"(c[0]), "+f"(c[1]), "+f"(c[2]), "+f"(c[3])
        : "r"(a0), "r"(a1), "r"(a2), "r"(a3), "r"(b0), "r"(b1));
}
__device__ __forceinline__ void ldsm4(uint32_t& r0, uint32_t& r1, uint32_t& r2,
                                      uint32_t& r3, const void* p) {
    uint32_t a = (uint32_t)__cvta_generic_to_shared(p);
    asm volatile("ldmatrix.sync.aligned.m8n8.x4.shared.b16 {%0,%1,%2,%3}, [%4];"
                 : "=r"(r0), "=r"(r1), "=r"(r2), "=r"(r3) : "r"(a));
}
__device__ __forceinline__ void ldsm4t(uint32_t& r0, uint32_t& r1, uint32_t& r2,
                                       uint32_t& r3, const void* p) {
    uint32_t a = (uint32_t)__cvta_generic_to_shared(p);
    asm volatile("ldmatrix.sync.aligned.m8n8.x4.trans.shared.b16 {%0,%1,%2,%3}, [%4];"
                 : "=r"(r0), "=r"(r1), "=r"(r2), "=r"(r3) : "r"(a));
}
__device__ __forceinline__ void cp16(void* smem, const void* gmem) {
    uint32_t s = (uint32_t)__cvta_generic_to_shared(smem);
    asm volatile("cp.async.cg.shared.global [%0], [%1], 16;" :: "r"(s), "l"(gmem));
}
__device__ __forceinline__ uint32_t packbf(float lo, float hi) {
    __nv_bfloat162 v = __floats2bfloat162_rn(lo, hi);
    return *(uint32_t*)&v;
}

// ---------------------------------------------------------------------------
// LayerNorm -> bf16
// ---------------------------------------------------------------------------
__global__ void ln_kernel(const float* __restrict__ x,
                          const float* __restrict__ gamma,
                          const float* __restrict__ beta,
                          __nv_bfloat16* __restrict__ out) {
    int row = blockIdx.x;
    int tid = threadIdx.x;
    const float4* xr = (const float4*)(x + (size_t)row * E_);
    float4 v = xr[tid];
    float s  = v.x + v.y + v.z + v.w;
    float ss = v.x*v.x + v.y*v.y + v.z*v.z + v.w*v.w;
    #pragma unroll
    for (int o = 16; o; o >>= 1) {
        s  += __shfl_xor_sync(0xFFFFFFFFu, s,  o);
        ss += __shfl_xor_sync(0xFFFFFFFFu, ss, o);
    }
    __shared__ float rs[8], rss[8], stats[2];
    int w = tid >> 5, l = tid & 31;
    if (l == 0) { rs[w] = s; rss[w] = ss; }
    __syncthreads();
    if (w == 0) {
        s  = (l < 8) ? rs[l]  : 0.f;
        ss = (l < 8) ? rss[l] : 0.f;
        #pragma unroll
        for (int o = 4; o; o >>= 1) {
            s  += __shfl_xor_sync(0xFFFFFFFFu, s,  o);
            ss += __shfl_xor_sync(0xFFFFFFFFu, ss, o);
        }
        if (l == 0) {
            float mean = s * (1.f / E_);
            float var  = ss * (1.f / E_) - mean * mean;
            stats[0] = mean;
            stats[1] = rsqrtf(var + 1e-5f);
        }
    }
    __syncthreads();
    float mean = stats[0], rstd = stats[1];
    float4 gv = ((const float4*)gamma)[tid];
    float4 bv = ((const float4*)beta)[tid];
    float ox = (v.x - mean) * rstd * gv.x + bv.x;
    float oy = (v.y - mean) * rstd * gv.y + bv.y;
    float oz = (v.z - mean) * rstd * gv.z + bv.z;
    float ow = (v.w - mean) * rstd * gv.w + bv.w;
    __nv_bfloat162* op = (__nv_bfloat162*)(out + (size_t)row * E_);
    op[2*tid]   = __floats2bfloat162_rn(ox, oy);
    op[2*tid+1] = __floats2bfloat162_rn(oz, ow);
}

__global__ void conv_w(const float4* __restrict__ in,
                       __nv_bfloat162* __restrict__ out, int n4) {
    int i = blockIdx.x * blockDim.x + threadIdx.x;
    if (i < n4) {
        float4 v = in[i];
        out[2*i]   = __floats2bfloat162_rn(v.x, v.y);
        out[2*i+1] = __floats2bfloat162_rn(v.z, v.w);
    }
}

// ---------------------------------------------------------------------------
// BF16 GEMM NT: A[M,K]*B[N,K]^T. 128x128 tile, BK=32, 8 warps (2m x 4n),
// warp 64x32, ldmatrix + HMMA.16816. 4-stage cp.async, 1 sync per BK iter,
// register double-buffered fragments. Out: Cb(bf16) else C(fp32,+resid).
// ---------------------------------------------------------------------------
#define LDB_ 40
#define GST  (128 * LDB_)                       // bf16 elems per stage per matrix
#define GEMM_DSMEM (8 * GST * 2)                // 4 stages x (A+B) = 81920 B

__global__ void __launch_bounds__(256, 2)
gemm_bf16(const __nv_bfloat16* __restrict__ A, const __nv_bfloat16* __restrict__ Bm,
          const float* __restrict__ resid, float* __restrict__ C,
          __nv_bfloat16* __restrict__ Cb,
          int M, int N, int K) {
    extern __shared__ __nv_bfloat16 dsm[];
    __nv_bfloat16* As = dsm;              // [4][128][40]
    __nv_bfloat16* Bs = dsm + 4 * GST;    // [4][128][40]

    int tid  = threadIdx.x;
    int lane = tid & 31, w = tid >> 5;
    int q = lane & 3, rr = lane >> 2;
    int wm = w & 1, wn = w >> 1;
    int m0b = blockIdx.y * 128, n0b = blockIdx.x * 128;

    int r0 = tid >> 2, ch = tid & 3;
    const __nv_bfloat16* Ap0 = A  + (size_t)(m0b + r0)      * K + ch * 8;
    const __nv_bfloat16* Ap1 = A  + (size_t)(m0b + r0 + 64) * K + ch * 8;
    const __nv_bfloat16* Bp0 = Bm + (size_t)(n0b + r0)      * K + ch * 8;
    const __nv_bfloat16* Bp1 = Bm + (size_t)(n0b + r0 + 64) * K + ch * 8;

    auto stage = [&](int s) {
        int buf = s & 3;
        int k0 = s * 32;
        cp16(&As[(buf * 128 + r0)      * LDB_ + ch * 8], Ap0 + k0);
        cp16(&As[(buf * 128 + r0 + 64) * LDB_ + ch * 8], Ap1 + k0);
        cp16(&Bs[(buf * 128 + r0)      * LDB_ + ch * 8], Bp0 + k0);
        cp16(&Bs[(buf * 128 + r0 + 64) * LDB_ + ch * 8], Bp1 + k0);
        asm volatile("cp.async.commit_group;");
    };

    float acc[4][4][4];
    #pragma unroll
    for (int i = 0; i < 4; i++)
        #pragma unroll
        for (int j = 0; j < 4; j++)
            #pragma unroll
            for (int c = 0; c < 4; c++) acc[i][j][c] = 0.f;

    const int KS = K / 32;
    stage(0); stage(1); stage(2);

    for (int s = 0; s < KS; s++) {
        int pend = KS - 1 - s; if (pend > 2) pend = 2;
        if (pend == 2)      asm volatile("cp.async.wait_group 2;");
        else if (pend == 1) asm volatile("cp.async.wait_group 1;");
        else                asm volatile("cp.async.wait_group 0;");
        __syncthreads();
        if (s + 3 < KS) stage(s + 3);

        int buf = s & 3;
        uint32_t a[2][4][4], bq[2][2][4];
        auto lfr = [&](int ks, uint32_t av[4][4], uint32_t bv[2][4]) {
            #pragma unroll
            for (int mt = 0; mt < 4; mt++) {
                const __nv_bfloat16* p =
                    &As[(buf * 128 + wm*64 + mt*16 + (lane & 15)) * LDB_
                        + ks*16 + (lane >> 4) * 8];
                ldsm4(av[mt][0], av[mt][1], av[mt][2], av[mt][3], p);
            }
            #pragma unroll
            for (int np = 0; np < 2; np++) {
                int row = wn*32 + np*16 + ((lane >> 4) << 3) + (lane & 7);
                int col = ks*16 + ((lane >> 3) & 1) * 8;
                const __nv_bfloat16* p = &Bs[(buf * 128 + row) * LDB_ + col];
                ldsm4(bv[np][0], bv[np][1], bv[np][2], bv[np][3], p);
            }
        };

        lfr(0, a[0], bq[0]);
        #pragma unroll
        for (int ks = 0; ks < 2; ks++) {
            if (ks == 0) lfr(1, a[1], bq[1]);
            #pragma unroll
            for (int mt = 0; mt < 4; mt++)
                #pragma unroll
                for (int nt = 0; nt < 4; nt++) {
                    uint32_t b0 = bq[ks][nt >> 1][(nt & 1) * 2];
                    uint32_t b1 = bq[ks][nt >> 1][(nt & 1) * 2 + 1];
                    mma_bf16(acc[mt][nt], a[ks][mt][0], a[ks][mt][1],
                             a[ks][mt][2], a[ks][mt][3], b0, b1);
                }
        }
    }

    int mw = m0b + wm * 64, nw = n0b + wn * 32;
    #pragma unroll
    for (int mt = 0; mt < 4; mt++) {
        int row = mw + mt * 16 + rr;
        #pragma unroll
        for (int nt = 0; nt < 4; nt++) {
            int col = nw + nt * 8 + q * 2;
            size_t i0 = (size_t)row * N + col;
            size_t i1 = (size_t)(row + 8) * N + col;
            if (Cb) {
                *(__nv_bfloat162*)(Cb + i0) =
                    __floats2bfloat162_rn(acc[mt][nt][0], acc[mt][nt][1]);
                *(__nv_bfloat162*)(Cb + i1) =
                    __floats2bfloat162_rn(acc[mt][nt][2], acc[mt][nt][3]);
            } else {
                float2 v0 = make_float2(acc[mt][nt][0], acc[mt][nt][1]);
                float2 v1 = make_float2(acc[mt][nt][2], acc[mt][nt][3]);
                if (resid) {
                    float2 t0 = *(const float2*)(resid + i0);
                    float2 t1 = *(const float2*)(resid + i1);
                    v0.x += t0.x; v0.y += t0.y; v1.x += t1.x; v1.y += t1.y;
                }
                *(float2*)(C + i0) = v0;
                *(float2*)(C + i1) = v1;
            }
        }
    }
}

// ---------------------------------------------------------------------------
// Flash attention, bf16 HMMA. 3-buffer KV ring (1 sync/iter, prefetch depth 2),
// Q fragments hoisted to registers. Block = 128 q rows x one (b,h).
// ---------------------------------------------------------------------------
#define AT_LD 72
#define ATTN_SMEM ((128 * AT_LD + 3 * 2 * 64 * AT_LD) * 2)   // 73728 B

__global__ void __launch_bounds__(256, 2)
attn_bf16(const __nv_bfloat16* __restrict__ qkv, __nv_bfloat16* __restrict__ ctx) {
    extern __shared__ char smraw[];
    __nv_bfloat16* Qs = (__nv_bfloat16*)smraw;          // [128][72]
    __nv_bfloat16* KVs = Qs + 128 * AT_LD;              // [3][2][64][72]

    int tid  = threadIdx.x;
    int lane = tid & 31, w = tid >> 5;
    int gr = lane >> 2, q = lane & 3;
    int b = blockIdx.y & 1, h = blockIdx.y >> 1;
    int q0 = blockIdx.x * 128;
    const int NT = T_ / 64;

    // stage Q (rides with kv group 0)
    #pragma unroll
    for (int i = 0; i < 4; i++) {
        int c = tid + 256 * i;
        int row = c >> 3, ch = c & 7;
        const __nv_bfloat16* g =
            qkv + ((size_t)(q0 + row) * B_ + b) * (3 * E_) + h * HD_ + ch * 8;
        cp16(Qs + row * AT_LD + ch * 8, g);
    }

    auto issue_kv = [&](int it) {
        int buf = it % 3;
        __nv_bfloat16* Kb = KVs + buf * (2 * 64 * AT_LD);
        __nv_bfloat16* Vb = Kb + 64 * AT_LD;
        int k0 = it * 64;
        #pragma unroll
        for (int i = 0; i < 4; i++) {
            int c = tid + 256 * i;
            int kv = c >> 9;
            int idx = c & 511;
            int row = idx >> 3, ch = idx & 7;
            const __nv_bfloat16* g =
                qkv + ((size_t)(k0 + row) * B_ + b) * (3 * E_) + h * HD_ + ch * 8
                    + (kv ? 2 * E_ : E_);
            cp16((kv ? Vb : Kb) + row * AT_LD + ch * 8, g);
        }
        asm volatile("cp.async.commit_group;");
    };

    issue_kv(0);
    issue_kv(1);

    uint32_t qa[4][4];
    float p[8][4], o[8][4];
    #pragma unroll
    for (int nt = 0; nt < 8; nt++)
        #pragma unroll
        for (int c = 0; c < 4; c++) o[nt][c] = 0.f;
    float m0 = -1e30f, m1 = -1e30f, l0 = 0.f, l1 = 0.f;

    for (int it = 0; it < NT; it++) {
        if (it + 1 < NT) asm volatile("cp.async.wait_group 1;");
        else             asm volatile("cp.async.wait_group 0;");
        __syncthreads();
        if (it + 2 < NT) issue_kv(it + 2);

        if (it == 0) {
            #pragma unroll
            for (int ks = 0; ks < 4; ks++)
                ldsm4(qa[ks][0], qa[ks][1], qa[ks][2], qa[ks][3],
                      Qs + (w * 16 + (lane & 15)) * AT_LD + ks * 16 + (lane >> 4) * 8);
        }

        const __nv_bfloat16* Kb = KVs + (it % 3) * (2 * 64 * AT_LD);
        const __nv_bfloat16* Vb = Kb + 64 * AT_LD;

        // ---- S = Q K^T ----
        #pragma unroll
        for (int nt = 0; nt < 8; nt++)
            #pragma unroll
            for (int c = 0; c < 4; c++) p[nt][c] = 0.f;

        #pragma unroll
        for (int ks = 0; ks < 4; ks++) {
            #pragma unroll
            for (int np = 0; np < 4; np++) {
                uint32_t b0, b1, b2, b3;
                int row = np * 16 + ((lane >> 4) << 3) + (lane & 7);
                int col = ks * 16 + ((lane >> 3) & 1) * 8;
                ldsm4(b0, b1, b2, b3, Kb + row * AT_LD + col);
                mma_bf16(p[2 * np],     qa[ks][0], qa[ks][1], qa[ks][2], qa[ks][3], b0, b1);
                mma_bf16(p[2 * np + 1], qa[ks][0], qa[ks][1], qa[ks][2], qa[ks][3], b2, b3);
            }
        }

        // ---- scale + online softmax ----
        float mx0 = -1e30f, mx1 = -1e30f;
        #pragma unroll
        for (int nt = 0; nt < 8; nt++) {
            p[nt][0] *= 0.125f; p[nt][1] *= 0.125f;
            p[nt][2] *= 0.125f; p[nt][3] *= 0.125f;
            mx0 = fmaxf(mx0, fmaxf(p[nt][0], p[nt][1]));
            mx1 = fmaxf(mx1, fmaxf(p[nt][2], p[nt][3]));
        }
        mx0 = fmaxf(mx0, __shfl_xor_sync(0xFFFFFFFFu, mx0, 1));
        mx0 = fmaxf(mx0, __shfl_xor_sync(0xFFFFFFFFu, mx0, 2));
        mx1 = fmaxf(mx1, __shfl_xor_sync(0xFFFFFFFFu, mx1, 1));
        mx1 = fmaxf(mx1, __shfl_xor_sync(0xFFFFFFFFu, mx1, 2));
        float mn0 = fmaxf(m0, mx0), mn1 = fmaxf(m1, mx1);
        float cr0 = __expf(m0 - mn0), cr1 = __expf(m1 - mn1);
        m0 = mn0; m1 = mn1;
        float s0 = 0.f, s1 = 0.f;
        #pragma unroll
        for (int nt = 0; nt < 8; nt++) {
            p[nt][0] = __expf(p[nt][0] - mn0);
            p[nt][1] = __expf(p[nt][1] - mn0);
            p[nt][2] = __expf(p[nt][2] - mn1);
            p[nt][3] = __expf(p[nt][3] - mn1);
            s0 += p[nt][0] + p[nt][1];
            s1 += p[nt][2] + p[nt][3];
        }
        s0 += __shfl_xor_sync(0xFFFFFFFFu, s0, 1);
        s0 += __shfl_xor_sync(0xFFFFFFFFu, s0, 2);
        s1 += __shfl_xor_sync(0xFFFFFFFFu, s1, 1);
        s1 += __shfl_xor_sync(0xFFFFFFFFu, s1, 2);
        l0 = l0 * cr0 + s0;
        l1 = l1 * cr1 + s1;
        #pragma unroll
        for (int nt = 0; nt < 8; nt++) {
            o[nt][0] *= cr0; o[nt][1] *= cr0;
            o[nt][2] *= cr1; o[nt][3] *= cr1;
        }

        // ---- O += P V ----
        #pragma unroll
        for (int ks = 0; ks < 4; ks++) {
            uint32_t a0 = packbf(p[2*ks][0],   p[2*ks][1]);
            uint32_t a1 = packbf(p[2*ks][2],   p[2*ks][3]);
            uint32_t a2 = packbf(p[2*ks+1][0], p[2*ks+1][1]);
            uint32_t a3 = packbf(p[2*ks+1][2], p[2*ks+1][3]);
            #pragma unroll
            for (int np = 0; np < 4; np++) {
                uint32_t b0, b1, b2, b3;
                int row = ks * 16 + (lane & 15);
                int col = np * 16 + (lane >> 4) * 8;
                ldsm4t(b0, b1, b2, b3, Vb + row * AT_LD + col);
                mma_bf16(o[2 * np],     a0, a1, a2, a3, b0, b1);
                mma_bf16(o[2 * np + 1], a0, a1, a2, a3, b2, b3);
            }
        }
    }

    float i0 = 1.f / l0, i1 = 1.f / l1;
    int t0 = q0 + w * 16 + gr;
    #pragma unroll
    for (int nt = 0; nt < 8; nt++) {
        int d = h * HD_ + nt * 8 + 2 * q;
        *(__nv_bfloat162*)(ctx + ((size_t)t0 * B_ + b) * E_ + d) =
            __floats2bfloat162_rn(o[nt][0] * i0, o[nt][1] * i0);
        *(__nv_bfloat162*)(ctx + ((size_t)(t0 + 8) * B_ + b) * E_ + d) =
            __floats2bfloat162_rn(o[nt][2] * i1, o[nt][3] * i1);
    }
}

// ---------------------------------------------------------------------------
extern "C" void kernel_launch(void* const* d_in, const int* in_sizes, int n_in,
                              void* d_out, int out_size) {
    (void)in_sizes; (void)n_in; (void)out_size;
    const float* query = (const float*)d_in[0];
    const float* gamma = (const float*)d_in[1];
    const float* beta  = (const float*)d_in[2];
    const float* Win   = (const float*)d_in[3];   // [3E, E]
    const float* Wout  = (const float*)d_in[4];   // [E, E]
    float* out = (float*)d_out;

    __nv_bfloat16 *lnb, *qkvb, *ctxb, *wb;
    cudaGetSymbolAddress((void**)&lnb,  g_lnb);
    cudaGetSymbolAddress((void**)&qkvb, g_qkvb);
    cudaGetSymbolAddress((void**)&ctxb, g_ctxb);
    cudaGetSymbolAddress((void**)&wb,   g_wb);
    __nv_bfloat16* winb  = wb;
    __nv_bfloat16* woutb = wb + 3 * E_ * E_;

    cudaFuncSetAttribute(attn_bf16, cudaFuncAttributeMaxDynamicSharedMemorySize, ATTN_SMEM);
    cudaFuncSetAttribute(gemm_bf16, cudaFuncAttributeMaxDynamicSharedMemorySize, GEMM_DSMEM);

    // 0) weights -> bf16
    conv_w<<<(3 * E_ * E_ / 4 + 255) / 256, 256>>>((const float4*)Win,
                                                   (__nv_bfloat162*)winb, 3 * E_ * E_ / 4);
    conv_w<<<(E_ * E_ / 4 + 255) / 256, 256>>>((const float4*)Wout,
                                               (__nv_bfloat162*)woutb, E_ * E_ / 4);

    // 1) LayerNorm -> bf16
    ln_kernel<<<ROWS, 256>>>(query, gamma, beta, lnb);

    // 2) QKV projection
    dim3 g1(3 * E_ / 128, ROWS / 128);
    gemm_bf16<<<g1, 256, GEMM_DSMEM>>>(lnb, winb, nullptr, nullptr, qkvb, ROWS, 3 * E_, E_);

    // 3) Attention
    dim3 g2(T_ / 128, B_ * H_);
    attn_bf16<<<g2, 256, ATTN_SMEM>>>(qkvb, ctxb);

    // 4) Output projection + residual
    dim3 g3(E_ / 128, ROWS / 128);
    gemm_bf16<<<g3, 256, GEMM_DSMEM>>>(ctxb, woutb, query, out, nullptr, ROWS, E_, E_);
}